// round 12
// baseline (speedup 1.0000x reference)
#include <cuda_runtime.h>
#include <cuda_bf16.h>
#include <cstdint>

#define BB 16
#define NN 2048
#define DG 512
#define DH 512
#define OUTD 512
#define KTOP 512

// ---------------- scratch (no cudaMalloc allowed) ----------------
__device__ float g_hb1[BB * OUTD];
__device__ float g_hb2[BB * OUTD];
__device__ unsigned int g_minbits[BB];
__device__ float g_dinv[BB * NN];
__device__ unsigned int g_T[BB * NN];
__device__ unsigned int g_eq[BB * NN];
// bf16 3-way split planes of e1 (A) and e2 (B)
__device__ __nv_bfloat16 g_a0[BB * NN * OUTD];
__device__ __nv_bfloat16 g_a1[BB * NN * OUTD];
__device__ __nv_bfloat16 g_a2[BB * NN * OUTD];
__device__ __nv_bfloat16 g_b0[BB * NN * OUTD];
__device__ __nv_bfloat16 g_b1[BB * NN * OUTD];
__device__ __nv_bfloat16 g_b2[BB * NN * OUTD];

__device__ __forceinline__ unsigned int fmap(float f) {
    unsigned int u = __float_as_uint(f);
    return (u & 0x80000000u) ? ~u : (u | 0x80000000u);
}
__device__ __forceinline__ float funmap(unsigned int m) {
    unsigned int u = (m & 0x80000000u) ? (m ^ 0x80000000u) : ~m;
    return __uint_as_float(u);
}
__device__ __forceinline__ uint32_t smem_u32(const void* p) {
    uint32_t a;
    asm("{ .reg .u64 t; cvta.to.shared.u64 t, %1; cvt.u32.u64 %0, t; }" : "=r"(a) : "l"(p));
    return a;
}
__device__ __forceinline__ void ldsm4(uint32_t* r, uint32_t addr) {
    asm volatile("ldmatrix.sync.aligned.m8n8.x4.shared.b16 {%0,%1,%2,%3}, [%4];"
                 : "=r"(r[0]), "=r"(r[1]), "=r"(r[2]), "=r"(r[3]) : "r"(addr));
}
__device__ __forceinline__ void mma_bf16(float* c, const uint32_t* a, uint32_t b0, uint32_t b1) {
    asm volatile(
        "mma.sync.aligned.m16n8k16.row.col.f32.bf16.bf16.f32 "
        "{%0,%1,%2,%3}, {%4,%5,%6,%7}, {%8,%9}, {%0,%1,%2,%3};"
        : "+f"(c[0]), "+f"(c[1]), "+f"(c[2]), "+f"(c[3])
        : "r"(a[0]), "r"(a[1]), "r"(a[2]), "r"(a[3]), "r"(b0), "r"(b1));
}
__device__ __forceinline__ void cp16(uint32_t saddr, const void* g) {
    asm volatile("cp.async.cg.shared.global [%0], [%1], 16;" :: "r"(saddr), "l"(g));
}
#define CP_COMMIT() asm volatile("cp.async.commit_group;" ::: "memory")
#define CP_WAIT1() asm volatile("cp.async.wait_group 1;" ::: "memory")
#define CP_WAIT0() asm volatile("cp.async.wait_group 0;" ::: "memory")

__global__ void k_init() {
    if (threadIdx.x < BB) g_minbits[threadIdx.x] = 0xFFFFFFFFu;
}

// per-batch hidden contribution
__global__ void k_hb(const float* __restrict__ hidden,
                     const float* __restrict__ W1,
                     const float* __restrict__ W2) {
    int b = blockIdx.x;
    int o = threadIdx.x;
    const float* h = hidden + b * DH;
    float a1 = 0.f, a2 = 0.f;
#pragma unroll 4
    for (int d = 0; d < DH; d++) {
        float hv = h[d];
        a1 = fmaf(hv, W1[(size_t)(DG + d) * OUTD + o], a1);
        a2 = fmaf(hv, W2[(size_t)(DG + d) * OUTD + o], a2);
    }
    g_hb1[b * OUTD + o] = a1;
    g_hb2[b * OUTD + o] = a2;
}

#define BM 128
#define BN2 256
#define BK2 8
#define TM 16
#define TN 8

// e1/e2 GEMM (SIMT fp32, bitwise-sequential K) with fused bf16 3-way split epilogue
__global__ __launch_bounds__(256, 1) void k_gemm1(
    const float* __restrict__ ge, const float* __restrict__ mask,
    const float* __restrict__ W1, const float* __restrict__ b1,
    const float* __restrict__ W2, const float* __restrict__ b2) {
    __shared__ float As[2][BK2][BM];
    __shared__ float Bs[2][BK2][BN2];
    int bn = blockIdx.x;
    int bm = blockIdx.y;
    int tid = threadIdx.x;
    int tx = tid & 31;
    int ty = tid >> 5;
    int row0 = bm * BM;
    int col0 = (bn & 1) * BN2;

    const float* W;
    const float* bias;
    const float* hb;
    __nv_bfloat16 *P0, *P1, *P2;
    if (bn < 2) {
        W = W1; bias = b1; hb = g_hb1;
        P0 = g_a0; P1 = g_a1; P2 = g_a2;
    } else {
        W = W2; bias = b2; hb = g_hb2;
        P0 = g_b0; P1 = g_b1; P2 = g_b2;
    }

    int a_row = tid >> 1;
    int a_k4 = (tid & 1) * 4;
    int b_k = tid >> 5;
    int b_n8 = (tid & 31) * 8;

    const float* agp = ge + (size_t)(row0 + a_row) * DG + a_k4;
    const float* bgp = W + (size_t)b_k * OUTD + col0 + b_n8;

    float acc[TM][TN];
#pragma unroll
    for (int i = 0; i < TM; i++)
#pragma unroll
        for (int j = 0; j < TN; j++) acc[i][j] = 0.f;

    {
        float4 pa = *(const float4*)agp;
        float4 pb0 = *(const float4*)bgp;
        float4 pb1 = *(const float4*)(bgp + 4);
        As[0][a_k4 + 0][a_row] = pa.x;
        As[0][a_k4 + 1][a_row] = pa.y;
        As[0][a_k4 + 2][a_row] = pa.z;
        As[0][a_k4 + 3][a_row] = pa.w;
        *(float4*)&Bs[0][b_k][b_n8] = pb0;
        *(float4*)&Bs[0][b_k][b_n8 + 4] = pb1;
    }
    __syncthreads();

    for (int k0 = 0; k0 < DG; k0 += BK2) {
        int buf = (k0 >> 3) & 1;
        float4 pa, pb0, pb1;
        bool more = (k0 + BK2) < DG;
        if (more) {
            pa = *(const float4*)(agp + k0 + BK2);
            pb0 = *(const float4*)(bgp + (size_t)(k0 + BK2) * OUTD);
            pb1 = *(const float4*)(bgp + (size_t)(k0 + BK2) * OUTD + 4);
        }
#pragma unroll
        for (int kk = 0; kk < BK2; kk++) {
            float4 a0 = *(const float4*)&As[buf][kk][ty * TM];
            float4 a1v = *(const float4*)&As[buf][kk][ty * TM + 4];
            float4 a2v = *(const float4*)&As[buf][kk][ty * TM + 8];
            float4 a3v = *(const float4*)&As[buf][kk][ty * TM + 12];
            float4 bv0 = *(const float4*)&Bs[buf][kk][tx * TN];
            float4 bv1 = *(const float4*)&Bs[buf][kk][tx * TN + 4];
            float av[TM] = {a0.x, a0.y, a0.z, a0.w, a1v.x, a1v.y, a1v.z, a1v.w,
                            a2v.x, a2v.y, a2v.z, a2v.w, a3v.x, a3v.y, a3v.z, a3v.w};
            float bv[TN] = {bv0.x, bv0.y, bv0.z, bv0.w, bv1.x, bv1.y, bv1.z, bv1.w};
#pragma unroll
            for (int i = 0; i < TM; i++)
#pragma unroll
                for (int j = 0; j < TN; j++) acc[i][j] = fmaf(av[i], bv[j], acc[i][j]);
        }
        if (more) {
            int nb = buf ^ 1;
            As[nb][a_k4 + 0][a_row] = pa.x;
            As[nb][a_k4 + 1][a_row] = pa.y;
            As[nb][a_k4 + 2][a_row] = pa.z;
            As[nb][a_k4 + 3][a_row] = pa.w;
            *(float4*)&Bs[nb][b_k][b_n8] = pb0;
            *(float4*)&Bs[nb][b_k][b_n8 + 4] = pb1;
        }
        __syncthreads();
    }

    int b = row0 >> 11;
    float hbn[TN], bnn[TN];
#pragma unroll
    for (int j = 0; j < TN; j++) {
        int n = col0 + tx * TN + j;
        hbn[j] = hb[b * OUTD + n];
        bnn[j] = bias[n];
    }
#pragma unroll
    for (int i = 0; i < TM; i++) {
        int m = row0 + ty * TM + i;
        float mk = mask[m];
        size_t base = (size_t)m * OUTD + col0 + tx * TN;
        __nv_bfloat16 hh[TN], mm_[TN], ll[TN];
#pragma unroll
        for (int j = 0; j < TN; j++) {
            float o = mk * (acc[i][j] + hbn[j]) + bnn[j];
            __nv_bfloat16 h = __float2bfloat16_rn(o);
            float r = o - __bfloat162float(h);
            __nv_bfloat16 md = __float2bfloat16_rn(r);
            float r2 = r - __bfloat162float(md);
            hh[j] = h;
            mm_[j] = md;
            ll[j] = __float2bfloat16_rn(r2);
        }
        *(uint4*)(P0 + base) = *(uint4*)hh;
        *(uint4*)(P1 + base) = *(uint4*)mm_;
        *(uint4*)(P2 + base) = *(uint4*)ll;
    }
}

// ---- tensor-core gemm2 v3: 128x64 CTA tile, 3-stage XOR-swizzled pipeline, 2 CTAs/SM ----
#define KC2 32
#define APL 8192                     // bytes per A plane (128 rows x 64B)
#define BPL 4096                     // bytes per B plane (64 rows x 64B)
#define STAGEB (3 * APL + 3 * BPL)   // 36864 bytes per stage
#define NSTG 3
#define SMEMB2 (NSTG * STAGEB)       // 110592 bytes
#define NCHK2 (OUTD / KC2)           // 16

__global__ __launch_bounds__(256, 2) void k_gemm2m(float* __restrict__ out) {
    extern __shared__ __nv_bfloat16 sm[];
    __shared__ unsigned int sMin;
    int tid = threadIdx.x;
    int wid = tid >> 5;
    int lane = tid & 31;
    int b = blockIdx.z;
    int row0 = blockIdx.y * 128;
    int col0 = blockIdx.x * 64;
    int wm = wid >> 1;  // 0..3 (32-row slices)
    int wn = wid & 1;   // 0..1 (32-col slices)

    if (tid == 0) sMin = 0xFFFFFFFFu;

    // loader: 4 threads/row, 16B each; XOR swizzle colbyte ^= (row&3)<<4
    int lrow = tid >> 2;                       // 0..63
    int lcb = (tid & 3) * 16;                  // byte col pre-swizzle
    uint32_t dstc = (uint32_t)(lrow * 64 + (lcb ^ ((lrow & 3) << 4)));
    size_t rA0 = ((size_t)(b << 11) + row0 + lrow) * OUTD + (tid & 3) * 8;
    size_t rA1 = rA0 + (size_t)64 * OUTD;
    size_t rB = ((size_t)(b << 11) + col0 + lrow) * OUTD + (tid & 3) * 8;
    uint32_t smb = smem_u32(sm);

#define LOAD_CHUNK2(kk0, stg)                                    \
    do {                                                         \
        uint32_t s0 = smb + (uint32_t)(stg) * STAGEB + dstc;     \
        cp16(s0 + 0 * APL, g_a0 + rA0 + (kk0));                  \
        cp16(s0 + 0 * APL + 4096, g_a0 + rA1 + (kk0));           \
        cp16(s0 + 1 * APL, g_a1 + rA0 + (kk0));                  \
        cp16(s0 + 1 * APL + 4096, g_a1 + rA1 + (kk0));           \
        cp16(s0 + 2 * APL, g_a2 + rA0 + (kk0));                  \
        cp16(s0 + 2 * APL + 4096, g_a2 + rA1 + (kk0));           \
        cp16(s0 + 3 * APL + 0 * BPL, g_b0 + rB + (kk0));         \
        cp16(s0 + 3 * APL + 1 * BPL, g_b1 + rB + (kk0));         \
        cp16(s0 + 3 * APL + 2 * BPL, g_b2 + rB + (kk0));         \
        CP_COMMIT();                                             \
    } while (0)

    float shh[2][4][4], srest[2][4][4];
#pragma unroll
    for (int mf = 0; mf < 2; mf++)
#pragma unroll
        for (int nf = 0; nf < 4; nf++)
#pragma unroll
            for (int q = 0; q < 4; q++) {
                shh[mf][nf][q] = 0.f;
                srest[mf][nf][q] = 0.f;
            }

    // fragment addressing (swizzle = (lane&3)<<4 for all ldsm patterns here)
    int swf = (lane & 3) << 4;
    uint32_t aRowOff = (uint32_t)((wm * 32 + (lane & 15)) * 64);
    uint32_t bRowOff = (uint32_t)((wn * 32 + (lane & 7) + ((lane >> 4) & 1) * 8) * 64);
    uint32_t aColSel = (uint32_t)((lane >> 4) * 16);
    uint32_t bColSel = (uint32_t)(((lane >> 3) & 1) * 16);

    LOAD_CHUNK2(0, 0);
    LOAD_CHUNK2(KC2, 1);

    for (int c = 0; c < NCHK2; c++) {
        if (c == NCHK2 - 1) {
            CP_WAIT0();
        } else {
            CP_WAIT1();
        }
        __syncthreads();
        if (c + 2 < NCHK2) LOAD_CHUNK2((c + 2) * KC2, (c + 2) % 3);

        uint32_t base = smb + (uint32_t)(c % 3) * STAGEB;

#pragma unroll
        for (int s = 0; s < 2; s++) {
            uint32_t afr[3][2][4];
            uint32_t bfr[3][2][4];
            {
                uint32_t acol = (uint32_t)((s * 32 + aColSel) ^ swf);
                uint32_t bcol = (uint32_t)((s * 32 + bColSel) ^ swf);
#pragma unroll
                for (int p = 0; p < 3; p++)
#pragma unroll
                    for (int mf = 0; mf < 2; mf++)
                        ldsm4(afr[p][mf], base + p * APL + aRowOff + mf * 1024 + acol);
#pragma unroll
                for (int p = 0; p < 3; p++)
#pragma unroll
                    for (int g = 0; g < 2; g++)
                        ldsm4(bfr[p][g], base + 3 * APL + p * BPL + bRowOff + g * 1024 + bcol);
            }
            // term-outer: t=0 hh -> shh; t=1..5 hm,mh,hl,mm,lh -> srest
            // (per-accumulator (k16, term) order identical to rounds 9-11: bitwise same)
            const int pa_t[6] = {0, 0, 1, 0, 1, 2};
            const int pb_t[6] = {0, 1, 0, 2, 1, 0};
#pragma unroll
            for (int t = 0; t < 6; t++) {
                int pa = pa_t[t], pb = pb_t[t];
                float (*dst)[4][4] = (t == 0) ? shh : srest;
#pragma unroll
                for (int mf = 0; mf < 2; mf++)
#pragma unroll
                    for (int nf = 0; nf < 4; nf++)
                        mma_bf16(dst[mf][nf], afr[pa][mf],
                                 bfr[pb][nf >> 1][(nf & 1) * 2],
                                 bfr[pb][nf >> 1][(nf & 1) * 2 + 1]);
            }
        }
    }

    // epilogue: v = rest + hh (one rounding) + fused per-batch min
    float lmin = 3.402823466e+38f;
    float* outb = out + (size_t)b * NN * NN;
#pragma unroll
    for (int mf = 0; mf < 2; mf++)
#pragma unroll
        for (int nf = 0; nf < 4; nf++) {
            int r = row0 + wm * 32 + mf * 16 + (lane >> 2);
            int cc = col0 + wn * 32 + nf * 8 + (lane & 3) * 2;
            float v0x = __fadd_rn(srest[mf][nf][0], shh[mf][nf][0]);
            float v0y = __fadd_rn(srest[mf][nf][1], shh[mf][nf][1]);
            float v1x = __fadd_rn(srest[mf][nf][2], shh[mf][nf][2]);
            float v1y = __fadd_rn(srest[mf][nf][3], shh[mf][nf][3]);
            *(float2*)(outb + (size_t)r * NN + cc) = make_float2(v0x, v0y);
            *(float2*)(outb + (size_t)(r + 8) * NN + cc) = make_float2(v1x, v1y);
            lmin = fminf(lmin, fminf(fminf(v0x, v0y), fminf(v1x, v1y)));
        }
#pragma unroll
    for (int off = 16; off > 0; off >>= 1)
        lmin = fminf(lmin, __shfl_xor_sync(0xFFFFFFFFu, lmin, off));
    __syncthreads();
    if (lane == 0) atomicMin(&sMin, fmap(lmin));
    __syncthreads();
    if (tid == 0) atomicMin(&g_minbits[b], sMin);
}

// ---------------- selection / apply (unchanged) ----------------
#define RT 256
#define EPT 8
__global__ __launch_bounds__(RT) void k_sel(const float* __restrict__ out,
                                            const float* __restrict__ mask) {
    __shared__ unsigned int hist[256];
    __shared__ unsigned int warpsum[8];
    __shared__ unsigned int s_digit, s_r;
    __shared__ float s_part[8];

    int row = blockIdx.x;
    int b = row >> 11;
    int tid = threadIdx.x;
    int lane = tid & 31;
    int warp = tid >> 5;
    float minb = funmap(g_minbits[b]);
    float mk = mask[row];
    const float* rp = out + (size_t)row * NN;

    float v[EPT];
    unsigned int key[EPT];
    {
        float4 x0 = *(const float4*)(rp + tid * EPT);
        float4 x1 = *(const float4*)(rp + tid * EPT + 4);
        float xv[8] = {x0.x, x0.y, x0.z, x0.w, x1.x, x1.y, x1.z, x1.w};
#pragma unroll
        for (int q = 0; q < EPT; q++) {
            v[q] = (xv[q] - minb) * mk;
            key[q] = fmap(v[q]);
        }
    }

    unsigned int prefix = 0;
    unsigned int r = KTOP;
#pragma unroll
    for (int shift = 24; shift >= 0; shift -= 8) {
        hist[tid] = 0;
        __syncthreads();
        unsigned int pmask = (shift == 24) ? 0u : (0xFFFFFFFFu << (shift + 8));
#pragma unroll
        for (int q = 0; q < EPT; q++) {
            unsigned int k = key[q];
            bool match = ((k & pmask) == prefix);
            unsigned int d = match ? ((k >> shift) & 0xFFu) : 0xFFFFFFFFu;
            unsigned int peers = __match_any_sync(0xFFFFFFFFu, d);
            if (match && (lane == (__ffs(peers) - 1)))
                atomicAdd(&hist[d], __popc(peers));
        }
        __syncthreads();
        unsigned int h = hist[tid];
        unsigned int s = h;
#pragma unroll
        for (int off = 1; off < 32; off <<= 1) {
            unsigned int t = __shfl_down_sync(0xFFFFFFFFu, s, off);
            if (lane + off < 32) s += t;
        }
        if (lane == 0) warpsum[warp] = s;
        __syncthreads();
        unsigned int woff = 0;
#pragma unroll
        for (int w = 0; w < 8; w++)
            if (w > warp) woff += warpsum[w];
        unsigned int suffix = s + woff;
        if (suffix >= r && suffix - h < r) {
            s_digit = (unsigned int)tid;
            s_r = r - (suffix - h);
        }
        __syncthreads();
        prefix |= (s_digit << shift);
        r = s_r;
    }
    unsigned int T = prefix;
    unsigned int eq_needed = r;

    float lsum = 0.f;
#pragma unroll
    for (int q = 0; q < EPT; q++)
        if (key[q] > T) lsum += v[q];
#pragma unroll
    for (int off = 16; off > 0; off >>= 1) lsum += __shfl_xor_sync(0xFFFFFFFFu, lsum, off);
    if (lane == 0) s_part[warp] = lsum;
    __syncthreads();
    if (tid == 0) {
        float tot = 0.f;
#pragma unroll
        for (int w = 0; w < 8; w++) tot += s_part[w];
        tot += (float)eq_needed * funmap(T);
        float d = (tot > 0.f) ? (1.0f / sqrtf(tot)) : 0.0f;
        g_dinv[row] = d;
        g_T[row] = T;
        g_eq[row] = eq_needed;
    }
}

__global__ __launch_bounds__(RT) void k_apply(float* __restrict__ out,
                                              const float* __restrict__ mask) {
    __shared__ unsigned int s_w[8];

    int row = blockIdx.x;
    int b = row >> 11;
    int tid = threadIdx.x;
    int lane = tid & 31;
    int warp = tid >> 5;
    float minb = funmap(g_minbits[b]);
    float mk = mask[row];
    unsigned int T = g_T[row];
    unsigned int eq = g_eq[row];
    float di = g_dinv[row];
    float* rp = out + (size_t)row * NN;

    float v[EPT];
    unsigned int key[EPT];
    {
        float4 x0 = *(const float4*)(rp + tid * EPT);
        float4 x1 = *(const float4*)(rp + tid * EPT + 4);
        float xv[8] = {x0.x, x0.y, x0.z, x0.w, x1.x, x1.y, x1.z, x1.w};
#pragma unroll
        for (int q = 0; q < EPT; q++) {
            v[q] = (xv[q] - minb) * mk;
            key[q] = fmap(v[q]);
        }
    }

    unsigned int cnt = 0;
#pragma unroll
    for (int q = 0; q < EPT; q++) cnt += (key[q] == T) ? 1u : 0u;
    unsigned int incl = cnt;
#pragma unroll
    for (int off = 1; off < 32; off <<= 1) {
        unsigned int t = __shfl_up_sync(0xFFFFFFFFu, incl, off);
        if (lane >= off) incl += t;
    }
    if (lane == 31) s_w[warp] = incl;
    __syncthreads();
    unsigned int woff = 0;
#pragma unroll
    for (int w = 0; w < 8; w++)
        if (w < warp) woff += s_w[w];
    unsigned int rank = woff + incl - cnt;

    float dj[EPT];
    {
        float4 d0 = *(const float4*)(g_dinv + ((size_t)b << 11) + tid * EPT);
        float4 d1 = *(const float4*)(g_dinv + ((size_t)b << 11) + tid * EPT + 4);
        dj[0] = d0.x; dj[1] = d0.y; dj[2] = d0.z; dj[3] = d0.w;
        dj[4] = d1.x; dj[5] = d1.y; dj[6] = d1.z; dj[7] = d1.w;
    }

    float o[EPT];
#pragma unroll
    for (int q = 0; q < EPT; q++) {
        unsigned int k = key[q];
        bool keep = (k > T) || (k == T && rank < eq);
        if (k == T) rank++;
        o[q] = keep ? (di * v[q]) * dj[q] : 0.0f;
    }
    float4 y0 = make_float4(o[0], o[1], o[2], o[3]);
    float4 y1 = make_float4(o[4], o[5], o[6], o[7]);
    *(float4*)(rp + tid * EPT) = y0;
    *(float4*)(rp + tid * EPT + 4) = y1;
}

extern "C" void kernel_launch(void* const* d_in, const int* in_sizes, int n_in,
                              void* d_out, int out_size) {
    const float* ge = (const float*)d_in[0];
    const float* mask = (const float*)d_in[1];
    const float* hs = (const float*)d_in[2];
    const float* W1 = (const float*)d_in[3];
    const float* b1 = (const float*)d_in[4];
    const float* W2 = (const float*)d_in[5];
    const float* b2 = (const float*)d_in[6];
    float* out = (float*)d_out;

    cudaFuncSetAttribute(k_gemm2m, cudaFuncAttributeMaxDynamicSharedMemorySize, SMEMB2);

    k_init<<<1, 32>>>();
    k_hb<<<BB, 512>>>(hs, W1, W2);
    k_gemm1<<<dim3(4, (BB * NN) / BM), 256>>>(ge, mask, W1, b1, W2, b2);
    k_gemm2m<<<dim3(NN / 64, NN / 128, BB), 256, SMEMB2>>>(out);
    k_sel<<<BB * NN, RT>>>(out, mask);
    k_apply<<<BB * NN, RT>>>(out, mask);
}

// round 13
// speedup vs baseline: 1.0390x; 1.0390x over previous
#include <cuda_runtime.h>
#include <cuda_bf16.h>
#include <cstdint>

#define BB 16
#define NN 2048
#define DG 512
#define DH 512
#define OUTD 512
#define KTOP 512

// ---------------- scratch (no cudaMalloc allowed) ----------------
__device__ float g_hb1[BB * OUTD];
__device__ float g_hb2[BB * OUTD];
__device__ unsigned int g_minbits[BB];
__device__ float g_dinv[BB * NN];
__device__ unsigned int g_T[BB * NN];
__device__ unsigned int g_eq[BB * NN];
// bf16 3-way split planes of e1 (A) and e2 (B)
__device__ __nv_bfloat16 g_a0[BB * NN * OUTD];
__device__ __nv_bfloat16 g_a1[BB * NN * OUTD];
__device__ __nv_bfloat16 g_a2[BB * NN * OUTD];
__device__ __nv_bfloat16 g_b0[BB * NN * OUTD];
__device__ __nv_bfloat16 g_b1[BB * NN * OUTD];
__device__ __nv_bfloat16 g_b2[BB * NN * OUTD];

__device__ __forceinline__ unsigned int fmap(float f) {
    unsigned int u = __float_as_uint(f);
    return (u & 0x80000000u) ? ~u : (u | 0x80000000u);
}
__device__ __forceinline__ float funmap(unsigned int m) {
    unsigned int u = (m & 0x80000000u) ? (m ^ 0x80000000u) : ~m;
    return __uint_as_float(u);
}
__device__ __forceinline__ uint32_t smem_u32(const void* p) {
    uint32_t a;
    asm("{ .reg .u64 t; cvta.to.shared.u64 t, %1; cvt.u32.u64 %0, t; }" : "=r"(a) : "l"(p));
    return a;
}
__device__ __forceinline__ void ldsm4(uint32_t* r, uint32_t addr) {
    asm volatile("ldmatrix.sync.aligned.m8n8.x4.shared.b16 {%0,%1,%2,%3}, [%4];"
                 : "=r"(r[0]), "=r"(r[1]), "=r"(r[2]), "=r"(r[3]) : "r"(addr));
}
__device__ __forceinline__ void mma_bf16(float* c, const uint32_t* a, uint32_t b0, uint32_t b1) {
    asm volatile(
        "mma.sync.aligned.m16n8k16.row.col.f32.bf16.bf16.f32 "
        "{%0,%1,%2,%3}, {%4,%5,%6,%7}, {%8,%9}, {%0,%1,%2,%3};"
        : "+f"(c[0]), "+f"(c[1]), "+f"(c[2]), "+f"(c[3])
        : "r"(a[0]), "r"(a[1]), "r"(a[2]), "r"(a[3]), "r"(b0), "r"(b1));
}
__device__ __forceinline__ void cp16(uint32_t saddr, const void* g) {
    asm volatile("cp.async.cg.shared.global [%0], [%1], 16;" :: "r"(saddr), "l"(g));
}
#define CP_COMMIT() asm volatile("cp.async.commit_group;" ::: "memory")
#define CP_WAIT1() asm volatile("cp.async.wait_group 1;" ::: "memory")
#define CP_WAIT0() asm volatile("cp.async.wait_group 0;" ::: "memory")

__global__ void k_init() {
    if (threadIdx.x < BB) g_minbits[threadIdx.x] = 0xFFFFFFFFu;
}

// per-batch hidden contribution
__global__ void k_hb(const float* __restrict__ hidden,
                     const float* __restrict__ W1,
                     const float* __restrict__ W2) {
    int b = blockIdx.x;
    int o = threadIdx.x;
    const float* h = hidden + b * DH;
    float a1 = 0.f, a2 = 0.f;
#pragma unroll 4
    for (int d = 0; d < DH; d++) {
        float hv = h[d];
        a1 = fmaf(hv, W1[(size_t)(DG + d) * OUTD + o], a1);
        a2 = fmaf(hv, W2[(size_t)(DG + d) * OUTD + o], a2);
    }
    g_hb1[b * OUTD + o] = a1;
    g_hb2[b * OUTD + o] = a2;
}

#define BM 128
#define BN2 256
#define BK2 8
#define TM 16
#define TN 8

// e1/e2 GEMM (SIMT fp32, bitwise-sequential K) with fused bf16 3-way split epilogue
__global__ __launch_bounds__(256, 1) void k_gemm1(
    const float* __restrict__ ge, const float* __restrict__ mask,
    const float* __restrict__ W1, const float* __restrict__ b1,
    const float* __restrict__ W2, const float* __restrict__ b2) {
    __shared__ float As[2][BK2][BM];
    __shared__ float Bs[2][BK2][BN2];
    int bn = blockIdx.x;
    int bm = blockIdx.y;
    int tid = threadIdx.x;
    int tx = tid & 31;
    int ty = tid >> 5;
    int row0 = bm * BM;
    int col0 = (bn & 1) * BN2;

    const float* W;
    const float* bias;
    const float* hb;
    __nv_bfloat16 *P0, *P1, *P2;
    if (bn < 2) {
        W = W1; bias = b1; hb = g_hb1;
        P0 = g_a0; P1 = g_a1; P2 = g_a2;
    } else {
        W = W2; bias = b2; hb = g_hb2;
        P0 = g_b0; P1 = g_b1; P2 = g_b2;
    }

    int a_row = tid >> 1;
    int a_k4 = (tid & 1) * 4;
    int b_k = tid >> 5;
    int b_n8 = (tid & 31) * 8;

    const float* agp = ge + (size_t)(row0 + a_row) * DG + a_k4;
    const float* bgp = W + (size_t)b_k * OUTD + col0 + b_n8;

    float acc[TM][TN];
#pragma unroll
    for (int i = 0; i < TM; i++)
#pragma unroll
        for (int j = 0; j < TN; j++) acc[i][j] = 0.f;

    {
        float4 pa = *(const float4*)agp;
        float4 pb0 = *(const float4*)bgp;
        float4 pb1 = *(const float4*)(bgp + 4);
        As[0][a_k4 + 0][a_row] = pa.x;
        As[0][a_k4 + 1][a_row] = pa.y;
        As[0][a_k4 + 2][a_row] = pa.z;
        As[0][a_k4 + 3][a_row] = pa.w;
        *(float4*)&Bs[0][b_k][b_n8] = pb0;
        *(float4*)&Bs[0][b_k][b_n8 + 4] = pb1;
    }
    __syncthreads();

    for (int k0 = 0; k0 < DG; k0 += BK2) {
        int buf = (k0 >> 3) & 1;
        float4 pa, pb0, pb1;
        bool more = (k0 + BK2) < DG;
        if (more) {
            pa = *(const float4*)(agp + k0 + BK2);
            pb0 = *(const float4*)(bgp + (size_t)(k0 + BK2) * OUTD);
            pb1 = *(const float4*)(bgp + (size_t)(k0 + BK2) * OUTD + 4);
        }
#pragma unroll
        for (int kk = 0; kk < BK2; kk++) {
            float4 a0 = *(const float4*)&As[buf][kk][ty * TM];
            float4 a1v = *(const float4*)&As[buf][kk][ty * TM + 4];
            float4 a2v = *(const float4*)&As[buf][kk][ty * TM + 8];
            float4 a3v = *(const float4*)&As[buf][kk][ty * TM + 12];
            float4 bv0 = *(const float4*)&Bs[buf][kk][tx * TN];
            float4 bv1 = *(const float4*)&Bs[buf][kk][tx * TN + 4];
            float av[TM] = {a0.x, a0.y, a0.z, a0.w, a1v.x, a1v.y, a1v.z, a1v.w,
                            a2v.x, a2v.y, a2v.z, a2v.w, a3v.x, a3v.y, a3v.z, a3v.w};
            float bv[TN] = {bv0.x, bv0.y, bv0.z, bv0.w, bv1.x, bv1.y, bv1.z, bv1.w};
#pragma unroll
            for (int i = 0; i < TM; i++)
#pragma unroll
                for (int j = 0; j < TN; j++) acc[i][j] = fmaf(av[i], bv[j], acc[i][j]);
        }
        if (more) {
            int nb = buf ^ 1;
            As[nb][a_k4 + 0][a_row] = pa.x;
            As[nb][a_k4 + 1][a_row] = pa.y;
            As[nb][a_k4 + 2][a_row] = pa.z;
            As[nb][a_k4 + 3][a_row] = pa.w;
            *(float4*)&Bs[nb][b_k][b_n8] = pb0;
            *(float4*)&Bs[nb][b_k][b_n8 + 4] = pb1;
        }
        __syncthreads();
    }

    int b = row0 >> 11;
    float hbn[TN], bnn[TN];
#pragma unroll
    for (int j = 0; j < TN; j++) {
        int n = col0 + tx * TN + j;
        hbn[j] = hb[b * OUTD + n];
        bnn[j] = bias[n];
    }
#pragma unroll
    for (int i = 0; i < TM; i++) {
        int m = row0 + ty * TM + i;
        float mk = mask[m];
        size_t base = (size_t)m * OUTD + col0 + tx * TN;
        __nv_bfloat16 hh[TN], mm_[TN], ll[TN];
#pragma unroll
        for (int j = 0; j < TN; j++) {
            float o = mk * (acc[i][j] + hbn[j]) + bnn[j];
            __nv_bfloat16 h = __float2bfloat16_rn(o);
            float r = o - __bfloat162float(h);
            __nv_bfloat16 md = __float2bfloat16_rn(r);
            float r2 = r - __bfloat162float(md);
            hh[j] = h;
            mm_[j] = md;
            ll[j] = __float2bfloat16_rn(r2);
        }
        *(uint4*)(P0 + base) = *(uint4*)hh;
        *(uint4*)(P1 + base) = *(uint4*)mm_;
        *(uint4*)(P2 + base) = *(uint4*)ll;
    }
}

// ---- tensor-core gemm2 v3b: 128x64 CTA tile, 3-stage pipeline, FIXED XOR swizzle ----
// 64B rows; bank phase = row*4 mod 8 aliases rows {0,2,4,6}/{1,3,5,7}; swizzle key
// must be (row>>1)&3 (NOT row&3) to make those four rows hit distinct 16B banks.
#define KC2 32
#define APL 8192                     // bytes per A plane (128 rows x 64B)
#define BPL 4096                     // bytes per B plane (64 rows x 64B)
#define STAGEB (3 * APL + 3 * BPL)   // 36864 bytes per stage
#define NSTG 3
#define SMEMB2 (NSTG * STAGEB)       // 110592 bytes
#define NCHK2 (OUTD / KC2)           // 16

__global__ __launch_bounds__(256, 2) void k_gemm2m(float* __restrict__ out) {
    extern __shared__ __nv_bfloat16 sm[];
    __shared__ unsigned int sMin;
    int tid = threadIdx.x;
    int wid = tid >> 5;
    int lane = tid & 31;
    int b = blockIdx.z;
    int row0 = blockIdx.y * 128;
    int col0 = blockIdx.x * 64;
    int wm = wid >> 1;  // 0..3 (32-row slices)
    int wn = wid & 1;   // 0..1 (32-col slices)

    if (tid == 0) sMin = 0xFFFFFFFFu;

    // loader: 4 threads/row, 16B each; XOR swizzle colbyte ^= ((row>>1)&3)<<4
    int lrow = tid >> 2;                       // 0..63
    int lcb = (tid & 3) * 16;                  // byte col pre-swizzle
    uint32_t dstc = (uint32_t)(lrow * 64 + (lcb ^ (((lrow >> 1) & 3) << 4)));
    size_t rA0 = ((size_t)(b << 11) + row0 + lrow) * OUTD + (tid & 3) * 8;
    size_t rA1 = rA0 + (size_t)64 * OUTD;
    size_t rB = ((size_t)(b << 11) + col0 + lrow) * OUTD + (tid & 3) * 8;
    uint32_t smb = smem_u32(sm);

#define LOAD_CHUNK2(kk0, stg)                                    \
    do {                                                         \
        uint32_t s0 = smb + (uint32_t)(stg) * STAGEB + dstc;     \
        cp16(s0 + 0 * APL, g_a0 + rA0 + (kk0));                  \
        cp16(s0 + 0 * APL + 4096, g_a0 + rA1 + (kk0));           \
        cp16(s0 + 1 * APL, g_a1 + rA0 + (kk0));                  \
        cp16(s0 + 1 * APL + 4096, g_a1 + rA1 + (kk0));           \
        cp16(s0 + 2 * APL, g_a2 + rA0 + (kk0));                  \
        cp16(s0 + 2 * APL + 4096, g_a2 + rA1 + (kk0));           \
        cp16(s0 + 3 * APL + 0 * BPL, g_b0 + rB + (kk0));         \
        cp16(s0 + 3 * APL + 1 * BPL, g_b1 + rB + (kk0));         \
        cp16(s0 + 3 * APL + 2 * BPL, g_b2 + rB + (kk0));         \
        CP_COMMIT();                                             \
    } while (0)

    float shh[2][4][4], srest[2][4][4];
#pragma unroll
    for (int mf = 0; mf < 2; mf++)
#pragma unroll
        for (int nf = 0; nf < 4; nf++)
#pragma unroll
            for (int q = 0; q < 4; q++) {
                shh[mf][nf][q] = 0.f;
                srest[mf][nf][q] = 0.f;
            }

    // fragment addressing: for every ldsm pattern used here the row within its
    // 8-row phase is (lane&7) [A: lane&15 with +16 offsets ≡0 mod 8; B: +8/+16 ≡0],
    // so the swizzle key (row>>1)&3 == (lane>>1)&3 at all sites.
    int swf = ((lane >> 1) & 3) << 4;
    uint32_t aRowOff = (uint32_t)((wm * 32 + (lane & 15)) * 64);
    uint32_t bRowOff = (uint32_t)((wn * 32 + (lane & 7) + ((lane >> 4) & 1) * 8) * 64);
    uint32_t aColSel = (uint32_t)((lane >> 4) * 16);
    uint32_t bColSel = (uint32_t)(((lane >> 3) & 1) * 16);

    LOAD_CHUNK2(0, 0);
    LOAD_CHUNK2(KC2, 1);

    for (int c = 0; c < NCHK2; c++) {
        if (c == NCHK2 - 1) {
            CP_WAIT0();
        } else {
            CP_WAIT1();
        }
        __syncthreads();
        if (c + 2 < NCHK2) LOAD_CHUNK2((c + 2) * KC2, (c + 2) % 3);

        uint32_t base = smb + (uint32_t)(c % 3) * STAGEB;

#pragma unroll
        for (int s = 0; s < 2; s++) {
            uint32_t afr[3][2][4];
            uint32_t bfr[3][2][4];
            {
                uint32_t acol = (uint32_t)((s * 32 + aColSel) ^ swf);
                uint32_t bcol = (uint32_t)((s * 32 + bColSel) ^ swf);
#pragma unroll
                for (int p = 0; p < 3; p++)
#pragma unroll
                    for (int mf = 0; mf < 2; mf++)
                        ldsm4(afr[p][mf], base + p * APL + aRowOff + mf * 1024 + acol);
#pragma unroll
                for (int p = 0; p < 3; p++)
#pragma unroll
                    for (int g = 0; g < 2; g++)
                        ldsm4(bfr[p][g], base + 3 * APL + p * BPL + bRowOff + g * 1024 + bcol);
            }
            // term-outer: t=0 hh -> shh; t=1..5 hm,mh,hl,mm,lh -> srest
            // (per-accumulator (k16, term) order identical to rounds 9-12: bitwise same)
            const int pa_t[6] = {0, 0, 1, 0, 1, 2};
            const int pb_t[6] = {0, 1, 0, 2, 1, 0};
#pragma unroll
            for (int t = 0; t < 6; t++) {
                int pa = pa_t[t], pb = pb_t[t];
                float (*dst)[4][4] = (t == 0) ? shh : srest;
#pragma unroll
                for (int mf = 0; mf < 2; mf++)
#pragma unroll
                    for (int nf = 0; nf < 4; nf++)
                        mma_bf16(dst[mf][nf], afr[pa][mf],
                                 bfr[pb][nf >> 1][(nf & 1) * 2],
                                 bfr[pb][nf >> 1][(nf & 1) * 2 + 1]);
            }
        }
    }

    // epilogue: v = rest + hh (one rounding) + fused per-batch min
    float lmin = 3.402823466e+38f;
    float* outb = out + (size_t)b * NN * NN;
#pragma unroll
    for (int mf = 0; mf < 2; mf++)
#pragma unroll
        for (int nf = 0; nf < 4; nf++) {
            int r = row0 + wm * 32 + mf * 16 + (lane >> 2);
            int cc = col0 + wn * 32 + nf * 8 + (lane & 3) * 2;
            float v0x = __fadd_rn(srest[mf][nf][0], shh[mf][nf][0]);
            float v0y = __fadd_rn(srest[mf][nf][1], shh[mf][nf][1]);
            float v1x = __fadd_rn(srest[mf][nf][2], shh[mf][nf][2]);
            float v1y = __fadd_rn(srest[mf][nf][3], shh[mf][nf][3]);
            *(float2*)(outb + (size_t)r * NN + cc) = make_float2(v0x, v0y);
            *(float2*)(outb + (size_t)(r + 8) * NN + cc) = make_float2(v1x, v1y);
            lmin = fminf(lmin, fminf(fminf(v0x, v0y), fminf(v1x, v1y)));
        }
#pragma unroll
    for (int off = 16; off > 0; off >>= 1)
        lmin = fminf(lmin, __shfl_xor_sync(0xFFFFFFFFu, lmin, off));
    __syncthreads();
    if (lane == 0) atomicMin(&sMin, fmap(lmin));
    __syncthreads();
    if (tid == 0) atomicMin(&g_minbits[b], sMin);
}

// ---------------- selection / apply (unchanged) ----------------
#define RT 256
#define EPT 8
__global__ __launch_bounds__(RT) void k_sel(const float* __restrict__ out,
                                            const float* __restrict__ mask) {
    __shared__ unsigned int hist[256];
    __shared__ unsigned int warpsum[8];
    __shared__ unsigned int s_digit, s_r;
    __shared__ float s_part[8];

    int row = blockIdx.x;
    int b = row >> 11;
    int tid = threadIdx.x;
    int lane = tid & 31;
    int warp = tid >> 5;
    float minb = funmap(g_minbits[b]);
    float mk = mask[row];
    const float* rp = out + (size_t)row * NN;

    float v[EPT];
    unsigned int key[EPT];
    {
        float4 x0 = *(const float4*)(rp + tid * EPT);
        float4 x1 = *(const float4*)(rp + tid * EPT + 4);
        float xv[8] = {x0.x, x0.y, x0.z, x0.w, x1.x, x1.y, x1.z, x1.w};
#pragma unroll
        for (int q = 0; q < EPT; q++) {
            v[q] = (xv[q] - minb) * mk;
            key[q] = fmap(v[q]);
        }
    }

    unsigned int prefix = 0;
    unsigned int r = KTOP;
#pragma unroll
    for (int shift = 24; shift >= 0; shift -= 8) {
        hist[tid] = 0;
        __syncthreads();
        unsigned int pmask = (shift == 24) ? 0u : (0xFFFFFFFFu << (shift + 8));
#pragma unroll
        for (int q = 0; q < EPT; q++) {
            unsigned int k = key[q];
            bool match = ((k & pmask) == prefix);
            unsigned int d = match ? ((k >> shift) & 0xFFu) : 0xFFFFFFFFu;
            unsigned int peers = __match_any_sync(0xFFFFFFFFu, d);
            if (match && (lane == (__ffs(peers) - 1)))
                atomicAdd(&hist[d], __popc(peers));
        }
        __syncthreads();
        unsigned int h = hist[tid];
        unsigned int s = h;
#pragma unroll
        for (int off = 1; off < 32; off <<= 1) {
            unsigned int t = __shfl_down_sync(0xFFFFFFFFu, s, off);
            if (lane + off < 32) s += t;
        }
        if (lane == 0) warpsum[warp] = s;
        __syncthreads();
        unsigned int woff = 0;
#pragma unroll
        for (int w = 0; w < 8; w++)
            if (w > warp) woff += warpsum[w];
        unsigned int suffix = s + woff;
        if (suffix >= r && suffix - h < r) {
            s_digit = (unsigned int)tid;
            s_r = r - (suffix - h);
        }
        __syncthreads();
        prefix |= (s_digit << shift);
        r = s_r;
    }
    unsigned int T = prefix;
    unsigned int eq_needed = r;

    float lsum = 0.f;
#pragma unroll
    for (int q = 0; q < EPT; q++)
        if (key[q] > T) lsum += v[q];
#pragma unroll
    for (int off = 16; off > 0; off >>= 1) lsum += __shfl_xor_sync(0xFFFFFFFFu, lsum, off);
    if (lane == 0) s_part[warp] = lsum;
    __syncthreads();
    if (tid == 0) {
        float tot = 0.f;
#pragma unroll
        for (int w = 0; w < 8; w++) tot += s_part[w];
        tot += (float)eq_needed * funmap(T);
        float d = (tot > 0.f) ? (1.0f / sqrtf(tot)) : 0.0f;
        g_dinv[row] = d;
        g_T[row] = T;
        g_eq[row] = eq_needed;
    }
}

__global__ __launch_bounds__(RT) void k_apply(float* __restrict__ out,
                                              const float* __restrict__ mask) {
    __shared__ unsigned int s_w[8];

    int row = blockIdx.x;
    int b = row >> 11;
    int tid = threadIdx.x;
    int lane = tid & 31;
    int warp = tid >> 5;
    float minb = funmap(g_minbits[b]);
    float mk = mask[row];
    unsigned int T = g_T[row];
    unsigned int eq = g_eq[row];
    float di = g_dinv[row];
    float* rp = out + (size_t)row * NN;

    float v[EPT];
    unsigned int key[EPT];
    {
        float4 x0 = *(const float4*)(rp + tid * EPT);
        float4 x1 = *(const float4*)(rp + tid * EPT + 4);
        float xv[8] = {x0.x, x0.y, x0.z, x0.w, x1.x, x1.y, x1.z, x1.w};
#pragma unroll
        for (int q = 0; q < EPT; q++) {
            v[q] = (xv[q] - minb) * mk;
            key[q] = fmap(v[q]);
        }
    }

    unsigned int cnt = 0;
#pragma unroll
    for (int q = 0; q < EPT; q++) cnt += (key[q] == T) ? 1u : 0u;
    unsigned int incl = cnt;
#pragma unroll
    for (int off = 1; off < 32; off <<= 1) {
        unsigned int t = __shfl_up_sync(0xFFFFFFFFu, incl, off);
        if (lane >= off) incl += t;
    }
    if (lane == 31) s_w[warp] = incl;
    __syncthreads();
    unsigned int woff = 0;
#pragma unroll
    for (int w = 0; w < 8; w++)
        if (w < warp) woff += s_w[w];
    unsigned int rank = woff + incl - cnt;

    float dj[EPT];
    {
        float4 d0 = *(const float4*)(g_dinv + ((size_t)b << 11) + tid * EPT);
        float4 d1 = *(const float4*)(g_dinv + ((size_t)b << 11) + tid * EPT + 4);
        dj[0] = d0.x; dj[1] = d0.y; dj[2] = d0.z; dj[3] = d0.w;
        dj[4] = d1.x; dj[5] = d1.y; dj[6] = d1.z; dj[7] = d1.w;
    }

    float o[EPT];
#pragma unroll
    for (int q = 0; q < EPT; q++) {
        unsigned int k = key[q];
        bool keep = (k > T) || (k == T && rank < eq);
        if (k == T) rank++;
        o[q] = keep ? (di * v[q]) * dj[q] : 0.0f;
    }
    float4 y0 = make_float4(o[0], o[1], o[2], o[3]);
    float4 y1 = make_float4(o[4], o[5], o[6], o[7]);
    *(float4*)(rp + tid * EPT) = y0;
    *(float4*)(rp + tid * EPT + 4) = y1;
}

extern "C" void kernel_launch(void* const* d_in, const int* in_sizes, int n_in,
                              void* d_out, int out_size) {
    const float* ge = (const float*)d_in[0];
    const float* mask = (const float*)d_in[1];
    const float* hs = (const float*)d_in[2];
    const float* W1 = (const float*)d_in[3];
    const float* b1 = (const float*)d_in[4];
    const float* W2 = (const float*)d_in[5];
    const float* b2 = (const float*)d_in[6];
    float* out = (float*)d_out;

    cudaFuncSetAttribute(k_gemm2m, cudaFuncAttributeMaxDynamicSharedMemorySize, SMEMB2);

    k_init<<<1, 32>>>();
    k_hb<<<BB, 512>>>(hs, W1, W2);
    k_gemm1<<<dim3(4, (BB * NN) / BM), 256>>>(ge, mask, W1, b1, W2, b2);
    k_gemm2m<<<dim3(NN / 64, NN / 128, BB), 256, SMEMB2>>>(out);
    k_sel<<<BB * NN, RT>>>(out, mask);
    k_apply<<<BB * NN, RT>>>(out, mask);
}

// round 14
// speedup vs baseline: 1.1121x; 1.0703x over previous
#include <cuda_runtime.h>
#include <cuda_bf16.h>
#include <cstdint>

#define BB 16
#define NN 2048
#define DG 512
#define DH 512
#define OUTD 512
#define KTOP 512

// ---------------- scratch (no cudaMalloc allowed) ----------------
__device__ float g_hb1[BB * OUTD];
__device__ float g_hb2[BB * OUTD];
__device__ unsigned int g_minbits[BB];
__device__ float g_dinv[BB * NN];
__device__ unsigned int g_T[BB * NN];
__device__ unsigned int g_eq[BB * NN];
// bf16 3-way split planes of e1 (A) and e2 (B)
__device__ __nv_bfloat16 g_a0[BB * NN * OUTD];
__device__ __nv_bfloat16 g_a1[BB * NN * OUTD];
__device__ __nv_bfloat16 g_a2[BB * NN * OUTD];
__device__ __nv_bfloat16 g_b0[BB * NN * OUTD];
__device__ __nv_bfloat16 g_b1[BB * NN * OUTD];
__device__ __nv_bfloat16 g_b2[BB * NN * OUTD];

__device__ __forceinline__ unsigned int fmap(float f) {
    unsigned int u = __float_as_uint(f);
    return (u & 0x80000000u) ? ~u : (u | 0x80000000u);
}
__device__ __forceinline__ float funmap(unsigned int m) {
    unsigned int u = (m & 0x80000000u) ? (m ^ 0x80000000u) : ~m;
    return __uint_as_float(u);
}
__device__ __forceinline__ uint32_t smem_u32(const void* p) {
    uint32_t a;
    asm("{ .reg .u64 t; cvta.to.shared.u64 t, %1; cvt.u32.u64 %0, t; }" : "=r"(a) : "l"(p));
    return a;
}
__device__ __forceinline__ void ldsm4(uint32_t* r, uint32_t addr) {
    asm volatile("ldmatrix.sync.aligned.m8n8.x4.shared.b16 {%0,%1,%2,%3}, [%4];"
                 : "=r"(r[0]), "=r"(r[1]), "=r"(r[2]), "=r"(r[3]) : "r"(addr));
}
__device__ __forceinline__ void mma_bf16(float* c, const uint32_t* a, uint32_t b0, uint32_t b1) {
    asm volatile(
        "mma.sync.aligned.m16n8k16.row.col.f32.bf16.bf16.f32 "
        "{%0,%1,%2,%3}, {%4,%5,%6,%7}, {%8,%9}, {%0,%1,%2,%3};"
        : "+f"(c[0]), "+f"(c[1]), "+f"(c[2]), "+f"(c[3])
        : "r"(a[0]), "r"(a[1]), "r"(a[2]), "r"(a[3]), "r"(b0), "r"(b1));
}
__device__ __forceinline__ void cp16(uint32_t saddr, const void* g) {
    asm volatile("cp.async.cg.shared.global [%0], [%1], 16;" :: "r"(saddr), "l"(g));
}
#define CP_COMMIT() asm volatile("cp.async.commit_group;" ::: "memory")
#define CP_WAIT1() asm volatile("cp.async.wait_group 1;" ::: "memory")
#define CP_WAIT0() asm volatile("cp.async.wait_group 0;" ::: "memory")

// per-batch hidden contribution (+ min-bits init folded in)
__global__ void k_hb(const float* __restrict__ hidden,
                     const float* __restrict__ W1,
                     const float* __restrict__ W2) {
    int b = blockIdx.x;
    int o = threadIdx.x;
    if (o == 0) g_minbits[b] = 0xFFFFFFFFu;
    const float* h = hidden + b * DH;
    float a1 = 0.f, a2 = 0.f;
#pragma unroll 4
    for (int d = 0; d < DH; d++) {
        float hv = h[d];
        a1 = fmaf(hv, W1[(size_t)(DG + d) * OUTD + o], a1);
        a2 = fmaf(hv, W2[(size_t)(DG + d) * OUTD + o], a2);
    }
    g_hb1[b * OUTD + o] = a1;
    g_hb2[b * OUTD + o] = a2;
}

#define BM 128
#define BN2 256
#define BK2 8
#define TM 16
#define TN 8

// e1/e2 GEMM (SIMT fp32, bitwise-sequential K) with fused bf16 3-way split epilogue
__global__ __launch_bounds__(256, 1) void k_gemm1(
    const float* __restrict__ ge, const float* __restrict__ mask,
    const float* __restrict__ W1, const float* __restrict__ b1,
    const float* __restrict__ W2, const float* __restrict__ b2) {
    __shared__ float As[2][BK2][BM];
    __shared__ float Bs[2][BK2][BN2];
    int bn = blockIdx.x;
    int bm = blockIdx.y;
    int tid = threadIdx.x;
    int tx = tid & 31;
    int ty = tid >> 5;
    int row0 = bm * BM;
    int col0 = (bn & 1) * BN2;

    const float* W;
    const float* bias;
    const float* hb;
    __nv_bfloat16 *P0, *P1, *P2;
    if (bn < 2) {
        W = W1; bias = b1; hb = g_hb1;
        P0 = g_a0; P1 = g_a1; P2 = g_a2;
    } else {
        W = W2; bias = b2; hb = g_hb2;
        P0 = g_b0; P1 = g_b1; P2 = g_b2;
    }

    int a_row = tid >> 1;
    int a_k4 = (tid & 1) * 4;
    int b_k = tid >> 5;
    int b_n8 = (tid & 31) * 8;

    const float* agp = ge + (size_t)(row0 + a_row) * DG + a_k4;
    const float* bgp = W + (size_t)b_k * OUTD + col0 + b_n8;

    float acc[TM][TN];
#pragma unroll
    for (int i = 0; i < TM; i++)
#pragma unroll
        for (int j = 0; j < TN; j++) acc[i][j] = 0.f;

    {
        float4 pa = *(const float4*)agp;
        float4 pb0 = *(const float4*)bgp;
        float4 pb1 = *(const float4*)(bgp + 4);
        As[0][a_k4 + 0][a_row] = pa.x;
        As[0][a_k4 + 1][a_row] = pa.y;
        As[0][a_k4 + 2][a_row] = pa.z;
        As[0][a_k4 + 3][a_row] = pa.w;
        *(float4*)&Bs[0][b_k][b_n8] = pb0;
        *(float4*)&Bs[0][b_k][b_n8 + 4] = pb1;
    }
    __syncthreads();

    for (int k0 = 0; k0 < DG; k0 += BK2) {
        int buf = (k0 >> 3) & 1;
        float4 pa, pb0, pb1;
        bool more = (k0 + BK2) < DG;
        if (more) {
            pa = *(const float4*)(agp + k0 + BK2);
            pb0 = *(const float4*)(bgp + (size_t)(k0 + BK2) * OUTD);
            pb1 = *(const float4*)(bgp + (size_t)(k0 + BK2) * OUTD + 4);
        }
#pragma unroll
        for (int kk = 0; kk < BK2; kk++) {
            float4 a0 = *(const float4*)&As[buf][kk][ty * TM];
            float4 a1v = *(const float4*)&As[buf][kk][ty * TM + 4];
            float4 a2v = *(const float4*)&As[buf][kk][ty * TM + 8];
            float4 a3v = *(const float4*)&As[buf][kk][ty * TM + 12];
            float4 bv0 = *(const float4*)&Bs[buf][kk][tx * TN];
            float4 bv1 = *(const float4*)&Bs[buf][kk][tx * TN + 4];
            float av[TM] = {a0.x, a0.y, a0.z, a0.w, a1v.x, a1v.y, a1v.z, a1v.w,
                            a2v.x, a2v.y, a2v.z, a2v.w, a3v.x, a3v.y, a3v.z, a3v.w};
            float bv[TN] = {bv0.x, bv0.y, bv0.z, bv0.w, bv1.x, bv1.y, bv1.z, bv1.w};
#pragma unroll
            for (int i = 0; i < TM; i++)
#pragma unroll
                for (int j = 0; j < TN; j++) acc[i][j] = fmaf(av[i], bv[j], acc[i][j]);
        }
        if (more) {
            int nb = buf ^ 1;
            As[nb][a_k4 + 0][a_row] = pa.x;
            As[nb][a_k4 + 1][a_row] = pa.y;
            As[nb][a_k4 + 2][a_row] = pa.z;
            As[nb][a_k4 + 3][a_row] = pa.w;
            *(float4*)&Bs[nb][b_k][b_n8] = pb0;
            *(float4*)&Bs[nb][b_k][b_n8 + 4] = pb1;
        }
        __syncthreads();
    }

    int b = row0 >> 11;
    float hbn[TN], bnn[TN];
#pragma unroll
    for (int j = 0; j < TN; j++) {
        int n = col0 + tx * TN + j;
        hbn[j] = hb[b * OUTD + n];
        bnn[j] = bias[n];
    }
#pragma unroll
    for (int i = 0; i < TM; i++) {
        int m = row0 + ty * TM + i;
        float mk = mask[m];
        size_t base = (size_t)m * OUTD + col0 + tx * TN;
        __nv_bfloat16 hh[TN], mm_[TN], ll[TN];
#pragma unroll
        for (int j = 0; j < TN; j++) {
            float o = mk * (acc[i][j] + hbn[j]) + bnn[j];
            __nv_bfloat16 h = __float2bfloat16_rn(o);
            float r = o - __bfloat162float(h);
            __nv_bfloat16 md = __float2bfloat16_rn(r);
            float r2 = r - __bfloat162float(md);
            hh[j] = h;
            mm_[j] = md;
            ll[j] = __float2bfloat16_rn(r2);
        }
        *(uint4*)(P0 + base) = *(uint4*)hh;
        *(uint4*)(P1 + base) = *(uint4*)mm_;
        *(uint4*)(P2 + base) = *(uint4*)ll;
    }
}

// ---- tensor-core gemm2 (R11 config: 128x64 CTA tile, 32x32 warp tiles, 2 CTAs/SM,
//      padded 2-stage cp.async pipeline) — measured best: 1.064 ms, tensor 63.9% ----
#define KC2 32
#define ST2 40                      // padded row stride in bf16 elems (80B)
#define PLA (128 * ST2)             // A plane elems (5120)
#define PLB (64 * ST2)              // B plane elems (2560)
#define BUFE2 (3 * PLA + 3 * PLB)   // elems per buffer (23040)
#define SMEMB2 (2 * BUFE2 * 2)      // 92160 bytes
#define NCHK2 (OUTD / KC2)          // 16

__global__ __launch_bounds__(256, 2) void k_gemm2m(float* __restrict__ out) {
    extern __shared__ __nv_bfloat16 sm[];
    __shared__ unsigned int sMin;
    int tid = threadIdx.x;
    int wid = tid >> 5;
    int lane = tid & 31;
    int b = blockIdx.z;
    int row0 = blockIdx.y * 128;
    int col0 = blockIdx.x * 64;
    int wm = wid >> 1;  // 0..3 (32-row slices)
    int wn = wid & 1;   // 0..1 (32-col slices)

    if (tid == 0) sMin = 0xFFFFFFFFu;

    // loader geometry: 4 threads per row (16B each covering 64B = 32 bf16)
    int lrow = tid >> 2;       // 0..63
    int lg = (tid & 3) * 8;    // bf16 elem offset
    size_t rA0 = ((size_t)(b << 11) + row0 + lrow) * OUTD + lg;
    size_t rA1 = rA0 + (size_t)64 * OUTD;
    size_t rB = ((size_t)(b << 11) + col0 + lrow) * OUTD + lg;
    uint32_t smb = smem_u32(sm);
    uint32_t sA0 = smb + (uint32_t)(lrow * ST2 + lg) * 2;
    uint32_t sA1 = sA0 + 64 * ST2 * 2;
    uint32_t sB = smb + (uint32_t)(3 * PLA + lrow * ST2 + lg) * 2;

#define LOAD_CHUNK2(kk0, bufsel)                                        \
    do {                                                                \
        uint32_t bo_ = (uint32_t)(bufsel) * (BUFE2 * 2);                \
        cp16(sA0 + bo_ + 0 * (PLA * 2), g_a0 + rA0 + (kk0));            \
        cp16(sA1 + bo_ + 0 * (PLA * 2), g_a0 + rA1 + (kk0));            \
        cp16(sA0 + bo_ + 1 * (PLA * 2), g_a1 + rA0 + (kk0));            \
        cp16(sA1 + bo_ + 1 * (PLA * 2), g_a1 + rA1 + (kk0));            \
        cp16(sA0 + bo_ + 2 * (PLA * 2), g_a2 + rA0 + (kk0));            \
        cp16(sA1 + bo_ + 2 * (PLA * 2), g_a2 + rA1 + (kk0));            \
        cp16(sB + bo_ + 0 * (PLB * 2), g_b0 + rB + (kk0));              \
        cp16(sB + bo_ + 1 * (PLB * 2), g_b1 + rB + (kk0));              \
        cp16(sB + bo_ + 2 * (PLB * 2), g_b2 + rB + (kk0));              \
        CP_COMMIT();                                                    \
    } while (0)

    float shh[2][4][4], srest[2][4][4];
#pragma unroll
    for (int mf = 0; mf < 2; mf++)
#pragma unroll
        for (int nf = 0; nf < 4; nf++)
#pragma unroll
            for (int q = 0; q < 4; q++) {
                shh[mf][nf][q] = 0.f;
                srest[mf][nf][q] = 0.f;
            }

    LOAD_CHUNK2(0, 0);

    for (int c = 0; c < NCHK2; c++) {
        int buf = c & 1;
        uint32_t base = smb + buf * (BUFE2 * 2);
        bool more = (c + 1) < NCHK2;
        if (more) {
            LOAD_CHUNK2((c + 1) * KC2, buf ^ 1);
            CP_WAIT1();
        } else {
            CP_WAIT0();
        }
        __syncthreads();

#pragma unroll
        for (int s = 0; s < 2; s++) {
            uint32_t afr[3][2][4];
            uint32_t bfr[3][2][4];
            {
                int arow = wm * 32 + (lane & 15);
                int acol = s * 16 + (lane >> 4) * 8;
#pragma unroll
                for (int p = 0; p < 3; p++)
#pragma unroll
                    for (int mf = 0; mf < 2; mf++)
                        ldsm4(afr[p][mf],
                              base + (uint32_t)(p * PLA + (arow + mf * 16) * ST2 + acol) * 2);
                int nrow = wn * 32 + (lane & 7) + ((lane >> 4) & 1) * 8;
                int kcol = s * 16 + ((lane >> 3) & 1) * 8;
#pragma unroll
                for (int p = 0; p < 3; p++)
#pragma unroll
                    for (int g = 0; g < 2; g++)
                        ldsm4(bfr[p][g],
                              base + (uint32_t)(3 * PLA + p * PLB + (nrow + g * 16) * ST2 + kcol) * 2);
            }
            // term-outer: t=0 hh -> shh; t=1..5 hm,mh,hl,mm,lh -> srest
            // (per-accumulator (k16, term) order identical since round 9: bitwise same)
            const int pa_t[6] = {0, 0, 1, 0, 1, 2};
            const int pb_t[6] = {0, 1, 0, 2, 1, 0};
#pragma unroll
            for (int t = 0; t < 6; t++) {
                int pa = pa_t[t], pb = pb_t[t];
                float (*dst)[4][4] = (t == 0) ? shh : srest;
#pragma unroll
                for (int mf = 0; mf < 2; mf++)
#pragma unroll
                    for (int nf = 0; nf < 4; nf++)
                        mma_bf16(dst[mf][nf], afr[pa][mf],
                                 bfr[pb][nf >> 1][(nf & 1) * 2],
                                 bfr[pb][nf >> 1][(nf & 1) * 2 + 1]);
            }
        }
        __syncthreads();
    }

    // epilogue: v = rest + hh (one rounding) + fused per-batch min
    float lmin = 3.402823466e+38f;
    float* outb = out + (size_t)b * NN * NN;
#pragma unroll
    for (int mf = 0; mf < 2; mf++)
#pragma unroll
        for (int nf = 0; nf < 4; nf++) {
            int r = row0 + wm * 32 + mf * 16 + (lane >> 2);
            int cc = col0 + wn * 32 + nf * 8 + (lane & 3) * 2;
            float v0x = __fadd_rn(srest[mf][nf][0], shh[mf][nf][0]);
            float v0y = __fadd_rn(srest[mf][nf][1], shh[mf][nf][1]);
            float v1x = __fadd_rn(srest[mf][nf][2], shh[mf][nf][2]);
            float v1y = __fadd_rn(srest[mf][nf][3], shh[mf][nf][3]);
            *(float2*)(outb + (size_t)r * NN + cc) = make_float2(v0x, v0y);
            *(float2*)(outb + (size_t)(r + 8) * NN + cc) = make_float2(v1x, v1y);
            lmin = fminf(lmin, fminf(fminf(v0x, v0y), fminf(v1x, v1y)));
        }
#pragma unroll
    for (int off = 16; off > 0; off >>= 1)
        lmin = fminf(lmin, __shfl_xor_sync(0xFFFFFFFFu, lmin, off));
    __syncthreads();
    if (lane == 0) atomicMin(&sMin, fmap(lmin));
    __syncthreads();
    if (tid == 0) atomicMin(&g_minbits[b], sMin);
}

// ---------------- selection / apply (unchanged) ----------------
#define RT 256
#define EPT 8
__global__ __launch_bounds__(RT) void k_sel(const float* __restrict__ out,
                                            const float* __restrict__ mask) {
    __shared__ unsigned int hist[256];
    __shared__ unsigned int warpsum[8];
    __shared__ unsigned int s_digit, s_r;
    __shared__ float s_part[8];

    int row = blockIdx.x;
    int b = row >> 11;
    int tid = threadIdx.x;
    int lane = tid & 31;
    int warp = tid >> 5;
    float minb = funmap(g_minbits[b]);
    float mk = mask[row];
    const float* rp = out + (size_t)row * NN;

    float v[EPT];
    unsigned int key[EPT];
    {
        float4 x0 = *(const float4*)(rp + tid * EPT);
        float4 x1 = *(const float4*)(rp + tid * EPT + 4);
        float xv[8] = {x0.x, x0.y, x0.z, x0.w, x1.x, x1.y, x1.z, x1.w};
#pragma unroll
        for (int q = 0; q < EPT; q++) {
            v[q] = (xv[q] - minb) * mk;
            key[q] = fmap(v[q]);
        }
    }

    unsigned int prefix = 0;
    unsigned int r = KTOP;
#pragma unroll
    for (int shift = 24; shift >= 0; shift -= 8) {
        hist[tid] = 0;
        __syncthreads();
        unsigned int pmask = (shift == 24) ? 0u : (0xFFFFFFFFu << (shift + 8));
#pragma unroll
        for (int q = 0; q < EPT; q++) {
            unsigned int k = key[q];
            bool match = ((k & pmask) == prefix);
            unsigned int d = match ? ((k >> shift) & 0xFFu) : 0xFFFFFFFFu;
            unsigned int peers = __match_any_sync(0xFFFFFFFFu, d);
            if (match && (lane == (__ffs(peers) - 1)))
                atomicAdd(&hist[d], __popc(peers));
        }
        __syncthreads();
        unsigned int h = hist[tid];
        unsigned int s = h;
#pragma unroll
        for (int off = 1; off < 32; off <<= 1) {
            unsigned int t = __shfl_down_sync(0xFFFFFFFFu, s, off);
            if (lane + off < 32) s += t;
        }
        if (lane == 0) warpsum[warp] = s;
        __syncthreads();
        unsigned int woff = 0;
#pragma unroll
        for (int w = 0; w < 8; w++)
            if (w > warp) woff += warpsum[w];
        unsigned int suffix = s + woff;
        if (suffix >= r && suffix - h < r) {
            s_digit = (unsigned int)tid;
            s_r = r - (suffix - h);
        }
        __syncthreads();
        prefix |= (s_digit << shift);
        r = s_r;
    }
    unsigned int T = prefix;
    unsigned int eq_needed = r;

    float lsum = 0.f;
#pragma unroll
    for (int q = 0; q < EPT; q++)
        if (key[q] > T) lsum += v[q];
#pragma unroll
    for (int off = 16; off > 0; off >>= 1) lsum += __shfl_xor_sync(0xFFFFFFFFu, lsum, off);
    if (lane == 0) s_part[warp] = lsum;
    __syncthreads();
    if (tid == 0) {
        float tot = 0.f;
#pragma unroll
        for (int w = 0; w < 8; w++) tot += s_part[w];
        tot += (float)eq_needed * funmap(T);
        float d = (tot > 0.f) ? (1.0f / sqrtf(tot)) : 0.0f;
        g_dinv[row] = d;
        g_T[row] = T;
        g_eq[row] = eq_needed;
    }
}

__global__ __launch_bounds__(RT) void k_apply(float* __restrict__ out,
                                              const float* __restrict__ mask) {
    __shared__ unsigned int s_w[8];

    int row = blockIdx.x;
    int b = row >> 11;
    int tid = threadIdx.x;
    int lane = tid & 31;
    int warp = tid >> 5;
    float minb = funmap(g_minbits[b]);
    float mk = mask[row];
    unsigned int T = g_T[row];
    unsigned int eq = g_eq[row];
    float di = g_dinv[row];
    float* rp = out + (size_t)row * NN;

    float v[EPT];
    unsigned int key[EPT];
    {
        float4 x0 = *(const float4*)(rp + tid * EPT);
        float4 x1 = *(const float4*)(rp + tid * EPT + 4);
        float xv[8] = {x0.x, x0.y, x0.z, x0.w, x1.x, x1.y, x1.z, x1.w};
#pragma unroll
        for (int q = 0; q < EPT; q++) {
            v[q] = (xv[q] - minb) * mk;
            key[q] = fmap(v[q]);
        }
    }

    unsigned int cnt = 0;
#pragma unroll
    for (int q = 0; q < EPT; q++) cnt += (key[q] == T) ? 1u : 0u;
    unsigned int incl = cnt;
#pragma unroll
    for (int off = 1; off < 32; off <<= 1) {
        unsigned int t = __shfl_up_sync(0xFFFFFFFFu, incl, off);
        if (lane >= off) incl += t;
    }
    if (lane == 31) s_w[warp] = incl;
    __syncthreads();
    unsigned int woff = 0;
#pragma unroll
    for (int w = 0; w < 8; w++)
        if (w < warp) woff += s_w[w];
    unsigned int rank = woff + incl - cnt;

    float dj[EPT];
    {
        float4 d0 = *(const float4*)(g_dinv + ((size_t)b << 11) + tid * EPT);
        float4 d1 = *(const float4*)(g_dinv + ((size_t)b << 11) + tid * EPT + 4);
        dj[0] = d0.x; dj[1] = d0.y; dj[2] = d0.z; dj[3] = d0.w;
        dj[4] = d1.x; dj[5] = d1.y; dj[6] = d1.z; dj[7] = d1.w;
    }

    float o[EPT];
#pragma unroll
    for (int q = 0; q < EPT; q++) {
        unsigned int k = key[q];
        bool keep = (k > T) || (k == T && rank < eq);
        if (k == T) rank++;
        o[q] = keep ? (di * v[q]) * dj[q] : 0.0f;
    }
    float4 y0 = make_float4(o[0], o[1], o[2], o[3]);
    float4 y1 = make_float4(o[4], o[5], o[6], o[7]);
    *(float4*)(rp + tid * EPT) = y0;
    *(float4*)(rp + tid * EPT + 4) = y1;
}

extern "C" void kernel_launch(void* const* d_in, const int* in_sizes, int n_in,
                              void* d_out, int out_size) {
    const float* ge = (const float*)d_in[0];
    const float* mask = (const float*)d_in[1];
    const float* hs = (const float*)d_in[2];
    const float* W1 = (const float*)d_in[3];
    const float* b1 = (const float*)d_in[4];
    const float* W2 = (const float*)d_in[5];
    const float* b2 = (const float*)d_in[6];
    float* out = (float*)d_out;

    cudaFuncSetAttribute(k_gemm2m, cudaFuncAttributeMaxDynamicSharedMemorySize, SMEMB2);

    k_hb<<<BB, 512>>>(hs, W1, W2);
    k_gemm1<<<dim3(4, (BB * NN) / BM), 256>>>(ge, mask, W1, b1, W2, b2);
    k_gemm2m<<<dim3(NN / 64, NN / 128, BB), 256, SMEMB2>>>(out);
    k_sel<<<BB * NN, RT>>>(out, mask);
    k_apply<<<BB * NN, RT>>>(out, mask);
}

// round 15
// speedup vs baseline: 1.2513x; 1.1252x over previous
#include <cuda_runtime.h>
#include <cuda_bf16.h>
#include <cstdint>

#define BB 16
#define NN 2048
#define DG 512
#define DH 512
#define OUTD 512
#define KTOP 512

// ---------------- scratch (no cudaMalloc allowed) ----------------
__device__ float g_hb1[BB * OUTD];
__device__ float g_hb2[BB * OUTD];
__device__ unsigned int g_minbits[BB];
__device__ float g_dinv[BB * NN];
__device__ unsigned int g_T[BB * NN];
__device__ unsigned int g_eq[BB * NN];
// bf16 3-way split planes of e1 (A) and e2 (B)
__device__ __nv_bfloat16 g_a0[BB * NN * OUTD];
__device__ __nv_bfloat16 g_a1[BB * NN * OUTD];
__device__ __nv_bfloat16 g_a2[BB * NN * OUTD];
__device__ __nv_bfloat16 g_b0[BB * NN * OUTD];
__device__ __nv_bfloat16 g_b1[BB * NN * OUTD];
__device__ __nv_bfloat16 g_b2[BB * NN * OUTD];

__device__ __forceinline__ unsigned int fmap(float f) {
    unsigned int u = __float_as_uint(f);
    return (u & 0x80000000u) ? ~u : (u | 0x80000000u);
}
__device__ __forceinline__ float funmap(unsigned int m) {
    unsigned int u = (m & 0x80000000u) ? (m ^ 0x80000000u) : ~m;
    return __uint_as_float(u);
}
__device__ __forceinline__ uint32_t smem_u32(const void* p) {
    uint32_t a;
    asm("{ .reg .u64 t; cvta.to.shared.u64 t, %1; cvt.u32.u64 %0, t; }" : "=r"(a) : "l"(p));
    return a;
}
__device__ __forceinline__ void ldsm4(uint32_t* r, uint32_t addr) {
    asm volatile("ldmatrix.sync.aligned.m8n8.x4.shared.b16 {%0,%1,%2,%3}, [%4];"
                 : "=r"(r[0]), "=r"(r[1]), "=r"(r[2]), "=r"(r[3]) : "r"(addr));
}
__device__ __forceinline__ void mma_bf16(float* c, const uint32_t* a, uint32_t b0, uint32_t b1) {
    asm volatile(
        "mma.sync.aligned.m16n8k16.row.col.f32.bf16.bf16.f32 "
        "{%0,%1,%2,%3}, {%4,%5,%6,%7}, {%8,%9}, {%0,%1,%2,%3};"
        : "+f"(c[0]), "+f"(c[1]), "+f"(c[2]), "+f"(c[3])
        : "r"(a[0]), "r"(a[1]), "r"(a[2]), "r"(a[3]), "r"(b0), "r"(b1));
}
__device__ __forceinline__ void cp16(uint32_t saddr, const void* g) {
    asm volatile("cp.async.cg.shared.global [%0], [%1], 16;" :: "r"(saddr), "l"(g));
}
#define CP_COMMIT() asm volatile("cp.async.commit_group;" ::: "memory")
#define CP_WAIT1() asm volatile("cp.async.wait_group 1;" ::: "memory")
#define CP_WAIT0() asm volatile("cp.async.wait_group 0;" ::: "memory")

// per-batch hidden contribution (+ min-bits init folded in)
__global__ void k_hb(const float* __restrict__ hidden,
                     const float* __restrict__ W1,
                     const float* __restrict__ W2) {
    int b = blockIdx.x;
    int o = threadIdx.x;
    if (o == 0) g_minbits[b] = 0xFFFFFFFFu;
    const float* h = hidden + b * DH;
    float a1 = 0.f, a2 = 0.f;
#pragma unroll 4
    for (int d = 0; d < DH; d++) {
        float hv = h[d];
        a1 = fmaf(hv, W1[(size_t)(DG + d) * OUTD + o], a1);
        a2 = fmaf(hv, W2[(size_t)(DG + d) * OUTD + o], a2);
    }
    g_hb1[b * OUTD + o] = a1;
    g_hb2[b * OUTD + o] = a2;
}

#define BM 128
#define BN2 256
#define BK2 8
#define TM 16
#define TN 8

// e1/e2 GEMM (SIMT fp32, bitwise-sequential K) with fused bf16 3-way split epilogue
__global__ __launch_bounds__(256, 1) void k_gemm1(
    const float* __restrict__ ge, const float* __restrict__ mask,
    const float* __restrict__ W1, const float* __restrict__ b1,
    const float* __restrict__ W2, const float* __restrict__ b2) {
    __shared__ float As[2][BK2][BM];
    __shared__ float Bs[2][BK2][BN2];
    int bn = blockIdx.x;
    int bm = blockIdx.y;
    int tid = threadIdx.x;
    int tx = tid & 31;
    int ty = tid >> 5;
    int row0 = bm * BM;
    int col0 = (bn & 1) * BN2;

    const float* W;
    const float* bias;
    const float* hb;
    __nv_bfloat16 *P0, *P1, *P2;
    if (bn < 2) {
        W = W1; bias = b1; hb = g_hb1;
        P0 = g_a0; P1 = g_a1; P2 = g_a2;
    } else {
        W = W2; bias = b2; hb = g_hb2;
        P0 = g_b0; P1 = g_b1; P2 = g_b2;
    }

    int a_row = tid >> 1;
    int a_k4 = (tid & 1) * 4;
    int b_k = tid >> 5;
    int b_n8 = (tid & 31) * 8;

    const float* agp = ge + (size_t)(row0 + a_row) * DG + a_k4;
    const float* bgp = W + (size_t)b_k * OUTD + col0 + b_n8;

    float acc[TM][TN];
#pragma unroll
    for (int i = 0; i < TM; i++)
#pragma unroll
        for (int j = 0; j < TN; j++) acc[i][j] = 0.f;

    {
        float4 pa = *(const float4*)agp;
        float4 pb0 = *(const float4*)bgp;
        float4 pb1 = *(const float4*)(bgp + 4);
        As[0][a_k4 + 0][a_row] = pa.x;
        As[0][a_k4 + 1][a_row] = pa.y;
        As[0][a_k4 + 2][a_row] = pa.z;
        As[0][a_k4 + 3][a_row] = pa.w;
        *(float4*)&Bs[0][b_k][b_n8] = pb0;
        *(float4*)&Bs[0][b_k][b_n8 + 4] = pb1;
    }
    __syncthreads();

    for (int k0 = 0; k0 < DG; k0 += BK2) {
        int buf = (k0 >> 3) & 1;
        float4 pa, pb0, pb1;
        bool more = (k0 + BK2) < DG;
        if (more) {
            pa = *(const float4*)(agp + k0 + BK2);
            pb0 = *(const float4*)(bgp + (size_t)(k0 + BK2) * OUTD);
            pb1 = *(const float4*)(bgp + (size_t)(k0 + BK2) * OUTD + 4);
        }
#pragma unroll
        for (int kk = 0; kk < BK2; kk++) {
            float4 a0 = *(const float4*)&As[buf][kk][ty * TM];
            float4 a1v = *(const float4*)&As[buf][kk][ty * TM + 4];
            float4 a2v = *(const float4*)&As[buf][kk][ty * TM + 8];
            float4 a3v = *(const float4*)&As[buf][kk][ty * TM + 12];
            float4 bv0 = *(const float4*)&Bs[buf][kk][tx * TN];
            float4 bv1 = *(const float4*)&Bs[buf][kk][tx * TN + 4];
            float av[TM] = {a0.x, a0.y, a0.z, a0.w, a1v.x, a1v.y, a1v.z, a1v.w,
                            a2v.x, a2v.y, a2v.z, a2v.w, a3v.x, a3v.y, a3v.z, a3v.w};
            float bv[TN] = {bv0.x, bv0.y, bv0.z, bv0.w, bv1.x, bv1.y, bv1.z, bv1.w};
#pragma unroll
            for (int i = 0; i < TM; i++)
#pragma unroll
                for (int j = 0; j < TN; j++) acc[i][j] = fmaf(av[i], bv[j], acc[i][j]);
        }
        if (more) {
            int nb = buf ^ 1;
            As[nb][a_k4 + 0][a_row] = pa.x;
            As[nb][a_k4 + 1][a_row] = pa.y;
            As[nb][a_k4 + 2][a_row] = pa.z;
            As[nb][a_k4 + 3][a_row] = pa.w;
            *(float4*)&Bs[nb][b_k][b_n8] = pb0;
            *(float4*)&Bs[nb][b_k][b_n8 + 4] = pb1;
        }
        __syncthreads();
    }

    int b = row0 >> 11;
    float hbn[TN], bnn[TN];
#pragma unroll
    for (int j = 0; j < TN; j++) {
        int n = col0 + tx * TN + j;
        hbn[j] = hb[b * OUTD + n];
        bnn[j] = bias[n];
    }
#pragma unroll
    for (int i = 0; i < TM; i++) {
        int m = row0 + ty * TM + i;
        float mk = mask[m];
        size_t base = (size_t)m * OUTD + col0 + tx * TN;
        __nv_bfloat16 hh[TN], mm_[TN], ll[TN];
#pragma unroll
        for (int j = 0; j < TN; j++) {
            float o = mk * (acc[i][j] + hbn[j]) + bnn[j];
            __nv_bfloat16 h = __float2bfloat16_rn(o);
            float r = o - __bfloat162float(h);
            __nv_bfloat16 md = __float2bfloat16_rn(r);
            float r2 = r - __bfloat162float(md);
            hh[j] = h;
            mm_[j] = md;
            ll[j] = __float2bfloat16_rn(r2);
        }
        *(uint4*)(P0 + base) = *(uint4*)hh;
        *(uint4*)(P1 + base) = *(uint4*)mm_;
        *(uint4*)(P2 + base) = *(uint4*)ll;
    }
}

// ---- tensor-core gemm2 (R11 config: 128x64 CTA tile, 32x32 warp tiles, 2 CTAs/SM,
//      padded 2-stage cp.async pipeline) — measured best: 1.064 ms, tensor 63.9% ----
#define KC2 32
#define ST2 40                      // padded row stride in bf16 elems (80B)
#define PLA (128 * ST2)             // A plane elems (5120)
#define PLB (64 * ST2)              // B plane elems (2560)
#define BUFE2 (3 * PLA + 3 * PLB)   // elems per buffer (23040)
#define SMEMB2 (2 * BUFE2 * 2)      // 92160 bytes
#define NCHK2 (OUTD / KC2)          // 16

__global__ __launch_bounds__(256, 2) void k_gemm2m(float* __restrict__ out) {
    extern __shared__ __nv_bfloat16 sm[];
    __shared__ unsigned int sMin;
    int tid = threadIdx.x;
    int wid = tid >> 5;
    int lane = tid & 31;
    int b = blockIdx.z;
    int row0 = blockIdx.y * 128;
    int col0 = blockIdx.x * 64;
    int wm = wid >> 1;  // 0..3 (32-row slices)
    int wn = wid & 1;   // 0..1 (32-col slices)

    if (tid == 0) sMin = 0xFFFFFFFFu;

    // loader geometry: 4 threads per row (16B each covering 64B = 32 bf16)
    int lrow = tid >> 2;       // 0..63
    int lg = (tid & 3) * 8;    // bf16 elem offset
    size_t rA0 = ((size_t)(b << 11) + row0 + lrow) * OUTD + lg;
    size_t rA1 = rA0 + (size_t)64 * OUTD;
    size_t rB = ((size_t)(b << 11) + col0 + lrow) * OUTD + lg;
    uint32_t smb = smem_u32(sm);
    uint32_t sA0 = smb + (uint32_t)(lrow * ST2 + lg) * 2;
    uint32_t sA1 = sA0 + 64 * ST2 * 2;
    uint32_t sB = smb + (uint32_t)(3 * PLA + lrow * ST2 + lg) * 2;

#define LOAD_CHUNK2(kk0, bufsel)                                        \
    do {                                                                \
        uint32_t bo_ = (uint32_t)(bufsel) * (BUFE2 * 2);                \
        cp16(sA0 + bo_ + 0 * (PLA * 2), g_a0 + rA0 + (kk0));            \
        cp16(sA1 + bo_ + 0 * (PLA * 2), g_a0 + rA1 + (kk0));            \
        cp16(sA0 + bo_ + 1 * (PLA * 2), g_a1 + rA0 + (kk0));            \
        cp16(sA1 + bo_ + 1 * (PLA * 2), g_a1 + rA1 + (kk0));            \
        cp16(sA0 + bo_ + 2 * (PLA * 2), g_a2 + rA0 + (kk0));            \
        cp16(sA1 + bo_ + 2 * (PLA * 2), g_a2 + rA1 + (kk0));            \
        cp16(sB + bo_ + 0 * (PLB * 2), g_b0 + rB + (kk0));              \
        cp16(sB + bo_ + 1 * (PLB * 2), g_b1 + rB + (kk0));              \
        cp16(sB + bo_ + 2 * (PLB * 2), g_b2 + rB + (kk0));              \
        CP_COMMIT();                                                    \
    } while (0)

    float shh[2][4][4], srest[2][4][4];
#pragma unroll
    for (int mf = 0; mf < 2; mf++)
#pragma unroll
        for (int nf = 0; nf < 4; nf++)
#pragma unroll
            for (int q = 0; q < 4; q++) {
                shh[mf][nf][q] = 0.f;
                srest[mf][nf][q] = 0.f;
            }

    LOAD_CHUNK2(0, 0);

    for (int c = 0; c < NCHK2; c++) {
        int buf = c & 1;
        uint32_t base = smb + buf * (BUFE2 * 2);
        bool more = (c + 1) < NCHK2;
        if (more) {
            LOAD_CHUNK2((c + 1) * KC2, buf ^ 1);
            CP_WAIT1();
        } else {
            CP_WAIT0();
        }
        __syncthreads();

#pragma unroll
        for (int s = 0; s < 2; s++) {
            uint32_t afr[3][2][4];
            uint32_t bfr[3][2][4];
            {
                int arow = wm * 32 + (lane & 15);
                int acol = s * 16 + (lane >> 4) * 8;
#pragma unroll
                for (int p = 0; p < 3; p++)
#pragma unroll
                    for (int mf = 0; mf < 2; mf++)
                        ldsm4(afr[p][mf],
                              base + (uint32_t)(p * PLA + (arow + mf * 16) * ST2 + acol) * 2);
                int nrow = wn * 32 + (lane & 7) + ((lane >> 4) & 1) * 8;
                int kcol = s * 16 + ((lane >> 3) & 1) * 8;
#pragma unroll
                for (int p = 0; p < 3; p++)
#pragma unroll
                    for (int g = 0; g < 2; g++)
                        ldsm4(bfr[p][g],
                              base + (uint32_t)(3 * PLA + p * PLB + (nrow + g * 16) * ST2 + kcol) * 2);
            }
            // term-outer: t=0 hh -> shh; t=1..5 hm,mh,hl,mm,lh -> srest
            // (per-accumulator (k16, term) order identical since round 9: bitwise same)
            const int pa_t[6] = {0, 0, 1, 0, 1, 2};
            const int pb_t[6] = {0, 1, 0, 2, 1, 0};
#pragma unroll
            for (int t = 0; t < 6; t++) {
                int pa = pa_t[t], pb = pb_t[t];
                float (*dst)[4][4] = (t == 0) ? shh : srest;
#pragma unroll
                for (int mf = 0; mf < 2; mf++)
#pragma unroll
                    for (int nf = 0; nf < 4; nf++)
                        mma_bf16(dst[mf][nf], afr[pa][mf],
                                 bfr[pb][nf >> 1][(nf & 1) * 2],
                                 bfr[pb][nf >> 1][(nf & 1) * 2 + 1]);
            }
        }
        __syncthreads();
    }

    // epilogue: v = rest + hh (one rounding) + fused per-batch min
    float lmin = 3.402823466e+38f;
    float* outb = out + (size_t)b * NN * NN;
#pragma unroll
    for (int mf = 0; mf < 2; mf++)
#pragma unroll
        for (int nf = 0; nf < 4; nf++) {
            int r = row0 + wm * 32 + mf * 16 + (lane >> 2);
            int cc = col0 + wn * 32 + nf * 8 + (lane & 3) * 2;
            float v0x = __fadd_rn(srest[mf][nf][0], shh[mf][nf][0]);
            float v0y = __fadd_rn(srest[mf][nf][1], shh[mf][nf][1]);
            float v1x = __fadd_rn(srest[mf][nf][2], shh[mf][nf][2]);
            float v1y = __fadd_rn(srest[mf][nf][3], shh[mf][nf][3]);
            *(float2*)(outb + (size_t)r * NN + cc) = make_float2(v0x, v0y);
            *(float2*)(outb + (size_t)(r + 8) * NN + cc) = make_float2(v1x, v1y);
            lmin = fminf(lmin, fminf(fminf(v0x, v0y), fminf(v1x, v1y)));
        }
#pragma unroll
    for (int off = 16; off > 0; off >>= 1)
        lmin = fminf(lmin, __shfl_xor_sync(0xFFFFFFFFu, lmin, off));
    __syncthreads();
    if (lane == 0) atomicMin(&sMin, fmap(lmin));
    __syncthreads();
    if (tid == 0) atomicMin(&g_minbits[b], sMin);
}

// ---------------- selection (per-warp histograms, no match_any) / apply ----------------
#define RT 256
#define EPT 8
__global__ __launch_bounds__(RT) void k_sel(const float* __restrict__ out,
                                            const float* __restrict__ mask) {
    __shared__ unsigned int hist[8][256];   // per-warp private histograms
    __shared__ unsigned int warpsum[8];
    __shared__ unsigned int s_digit, s_r;
    __shared__ float s_part[8];

    int row = blockIdx.x;
    int b = row >> 11;
    int tid = threadIdx.x;
    int lane = tid & 31;
    int warp = tid >> 5;
    float minb = funmap(g_minbits[b]);
    float mk = mask[row];
    const float* rp = out + (size_t)row * NN;

    float v[EPT];
    unsigned int key[EPT];
    {
        float4 x0 = *(const float4*)(rp + tid * EPT);
        float4 x1 = *(const float4*)(rp + tid * EPT + 4);
        float xv[8] = {x0.x, x0.y, x0.z, x0.w, x1.x, x1.y, x1.z, x1.w};
#pragma unroll
        for (int q = 0; q < EPT; q++) {
            v[q] = (xv[q] - minb) * mk;
            key[q] = fmap(v[q]);
        }
    }

    unsigned int prefix = 0;
    unsigned int r = KTOP;
#pragma unroll
    for (int shift = 24; shift >= 0; shift -= 8) {
        // zero all 8 warp-histograms (2048 words / 256 threads = 8 each)
        unsigned int* hflat = &hist[0][0];
#pragma unroll
        for (int q = 0; q < 8; q++) hflat[tid + q * 256] = 0u;
        __syncthreads();
        unsigned int pmask = (shift == 24) ? 0u : (0xFFFFFFFFu << (shift + 8));
        unsigned int* hw = hist[warp];
#pragma unroll
        for (int q = 0; q < EPT; q++) {
            unsigned int k = key[q];
            if ((k & pmask) == prefix)
                atomicAdd(&hw[(k >> shift) & 0xFFu], 1u);
        }
        __syncthreads();
        // combine warp histograms for this thread's bin
        unsigned int h = 0;
#pragma unroll
        for (int w = 0; w < 8; w++) h += hist[w][tid];
        // suffix scan over 256 bins (warp shfl + cross-warp)
        unsigned int s = h;
#pragma unroll
        for (int off = 1; off < 32; off <<= 1) {
            unsigned int t = __shfl_down_sync(0xFFFFFFFFu, s, off);
            if (lane + off < 32) s += t;
        }
        if (lane == 0) warpsum[warp] = s;
        __syncthreads();
        unsigned int woff = 0;
#pragma unroll
        for (int w = 0; w < 8; w++)
            if (w > warp) woff += warpsum[w];
        unsigned int suffix = s + woff;  // sum over bins >= tid
        if (suffix >= r && suffix - h < r) {
            s_digit = (unsigned int)tid;
            s_r = r - (suffix - h);
        }
        __syncthreads();
        prefix |= (s_digit << shift);
        r = s_r;
    }
    unsigned int T = prefix;
    unsigned int eq_needed = r;

    float lsum = 0.f;
#pragma unroll
    for (int q = 0; q < EPT; q++)
        if (key[q] > T) lsum += v[q];
#pragma unroll
    for (int off = 16; off > 0; off >>= 1) lsum += __shfl_xor_sync(0xFFFFFFFFu, lsum, off);
    if (lane == 0) s_part[warp] = lsum;
    __syncthreads();
    if (tid == 0) {
        float tot = 0.f;
#pragma unroll
        for (int w = 0; w < 8; w++) tot += s_part[w];
        tot += (float)eq_needed * funmap(T);
        float d = (tot > 0.f) ? (1.0f / sqrtf(tot)) : 0.0f;
        g_dinv[row] = d;
        g_T[row] = T;
        g_eq[row] = eq_needed;
    }
}

__global__ __launch_bounds__(RT) void k_apply(float* __restrict__ out,
                                              const float* __restrict__ mask) {
    __shared__ unsigned int s_w[8];

    int row = blockIdx.x;
    int b = row >> 11;
    int tid = threadIdx.x;
    int lane = tid & 31;
    int warp = tid >> 5;
    float minb = funmap(g_minbits[b]);
    float mk = mask[row];
    unsigned int T = g_T[row];
    unsigned int eq = g_eq[row];
    float di = g_dinv[row];
    float* rp = out + (size_t)row * NN;

    float v[EPT];
    unsigned int key[EPT];
    {
        float4 x0 = *(const float4*)(rp + tid * EPT);
        float4 x1 = *(const float4*)(rp + tid * EPT + 4);
        float xv[8] = {x0.x, x0.y, x0.z, x0.w, x1.x, x1.y, x1.z, x1.w};
#pragma unroll
        for (int q = 0; q < EPT; q++) {
            v[q] = (xv[q] - minb) * mk;
            key[q] = fmap(v[q]);
        }
    }

    unsigned int cnt = 0;
#pragma unroll
    for (int q = 0; q < EPT; q++) cnt += (key[q] == T) ? 1u : 0u;
    unsigned int incl = cnt;
#pragma unroll
    for (int off = 1; off < 32; off <<= 1) {
        unsigned int t = __shfl_up_sync(0xFFFFFFFFu, incl, off);
        if (lane >= off) incl += t;
    }
    if (lane == 31) s_w[warp] = incl;
    __syncthreads();
    unsigned int woff = 0;
#pragma unroll
    for (int w = 0; w < 8; w++)
        if (w < warp) woff += s_w[w];
    unsigned int rank = woff + incl - cnt;

    float dj[EPT];
    {
        float4 d0 = *(const float4*)(g_dinv + ((size_t)b << 11) + tid * EPT);
        float4 d1 = *(const float4*)(g_dinv + ((size_t)b << 11) + tid * EPT + 4);
        dj[0] = d0.x; dj[1] = d0.y; dj[2] = d0.z; dj[3] = d0.w;
        dj[4] = d1.x; dj[5] = d1.y; dj[6] = d1.z; dj[7] = d1.w;
    }

    float o[EPT];
#pragma unroll
    for (int q = 0; q < EPT; q++) {
        unsigned int k = key[q];
        bool keep = (k > T) || (k == T && rank < eq);
        if (k == T) rank++;
        o[q] = keep ? (di * v[q]) * dj[q] : 0.0f;
    }
    float4 y0 = make_float4(o[0], o[1], o[2], o[3]);
    float4 y1 = make_float4(o[4], o[5], o[6], o[7]);
    *(float4*)(rp + tid * EPT) = y0;
    *(float4*)(rp + tid * EPT + 4) = y1;
}

extern "C" void kernel_launch(void* const* d_in, const int* in_sizes, int n_in,
                              void* d_out, int out_size) {
    const float* ge = (const float*)d_in[0];
    const float* mask = (const float*)d_in[1];
    const float* hs = (const float*)d_in[2];
    const float* W1 = (const float*)d_in[3];
    const float* b1 = (const float*)d_in[4];
    const float* W2 = (const float*)d_in[5];
    const float* b2 = (const float*)d_in[6];
    float* out = (float*)d_out;

    cudaFuncSetAttribute(k_gemm2m, cudaFuncAttributeMaxDynamicSharedMemorySize, SMEMB2);

    k_hb<<<BB, 512>>>(hs, W1, W2);
    k_gemm1<<<dim3(4, (BB * NN) / BM), 256>>>(ge, mask, W1, b1, W2, b2);
    k_gemm2m<<<dim3(NN / 64, NN / 128, BB), 256, SMEMB2>>>(out);
    k_sel<<<BB * NN, RT>>>(out, mask);
    k_apply<<<BB * NN, RT>>>(out, mask);
}

// round 16
// speedup vs baseline: 1.5725x; 1.2566x over previous
#include <cuda_runtime.h>
#include <cuda_fp16.h>
#include <cstdint>

#define BB 16
#define NN 2048
#define DG 512
#define DH 512
#define OUTD 512
#define KTOP 512

// ---------------- scratch (no cudaMalloc allowed) ----------------
__device__ float g_hb1[BB * OUTD];
__device__ float g_hb2[BB * OUTD];
__device__ unsigned int g_minbits[BB];
__device__ float g_dinv[BB * NN];
__device__ unsigned int g_T[BB * NN];
__device__ unsigned int g_eq[BB * NN];
// fp16 2-way split planes of e1 (A) and e2 (B): hi and mid
__device__ __half g_pa0[BB * NN * OUTD];
__device__ __half g_pa1[BB * NN * OUTD];
__device__ __half g_pb0[BB * NN * OUTD];
__device__ __half g_pb1[BB * NN * OUTD];

__device__ __forceinline__ unsigned int fmap(float f) {
    unsigned int u = __float_as_uint(f);
    return (u & 0x80000000u) ? ~u : (u | 0x80000000u);
}
__device__ __forceinline__ float funmap(unsigned int m) {
    unsigned int u = (m & 0x80000000u) ? (m ^ 0x80000000u) : ~m;
    return __uint_as_float(u);
}
__device__ __forceinline__ uint32_t smem_u32(const void* p) {
    uint32_t a;
    asm("{ .reg .u64 t; cvta.to.shared.u64 t, %1; cvt.u32.u64 %0, t; }" : "=r"(a) : "l"(p));
    return a;
}
__device__ __forceinline__ void ldsm4(uint32_t* r, uint32_t addr) {
    asm volatile("ldmatrix.sync.aligned.m8n8.x4.shared.b16 {%0,%1,%2,%3}, [%4];"
                 : "=r"(r[0]), "=r"(r[1]), "=r"(r[2]), "=r"(r[3]) : "r"(addr));
}
__device__ __forceinline__ void mma_f16(float* c, const uint32_t* a, uint32_t b0, uint32_t b1) {
    asm volatile(
        "mma.sync.aligned.m16n8k16.row.col.f32.f16.f16.f32 "
        "{%0,%1,%2,%3}, {%4,%5,%6,%7}, {%8,%9}, {%0,%1,%2,%3};"
        : "+f"(c[0]), "+f"(c[1]), "+f"(c[2]), "+f"(c[3])
        : "r"(a[0]), "r"(a[1]), "r"(a[2]), "r"(a[3]), "r"(b0), "r"(b1));
}
__device__ __forceinline__ void cp16(uint32_t saddr, const void* g) {
    asm volatile("cp.async.cg.shared.global [%0], [%1], 16;" :: "r"(saddr), "l"(g));
}
#define CP_COMMIT() asm volatile("cp.async.commit_group;" ::: "memory")
#define CP_WAIT1() asm volatile("cp.async.wait_group 1;" ::: "memory")
#define CP_WAIT0() asm volatile("cp.async.wait_group 0;" ::: "memory")

// per-batch hidden contribution (+ min-bits init folded in)
__global__ void k_hb(const float* __restrict__ hidden,
                     const float* __restrict__ W1,
                     const float* __restrict__ W2) {
    int b = blockIdx.x;
    int o = threadIdx.x;
    if (o == 0) g_minbits[b] = 0xFFFFFFFFu;
    const float* h = hidden + b * DH;
    float a1 = 0.f, a2 = 0.f;
#pragma unroll 4
    for (int d = 0; d < DH; d++) {
        float hv = h[d];
        a1 = fmaf(hv, W1[(size_t)(DG + d) * OUTD + o], a1);
        a2 = fmaf(hv, W2[(size_t)(DG + d) * OUTD + o], a2);
    }
    g_hb1[b * OUTD + o] = a1;
    g_hb2[b * OUTD + o] = a2;
}

#define BM 128
#define BN2 256
#define BK2 8
#define TM 16
#define TN 8

// e1/e2 GEMM (SIMT fp32, bitwise-sequential K) with fused fp16 2-way split epilogue
__global__ __launch_bounds__(256, 1) void k_gemm1(
    const float* __restrict__ ge, const float* __restrict__ mask,
    const float* __restrict__ W1, const float* __restrict__ b1,
    const float* __restrict__ W2, const float* __restrict__ b2) {
    __shared__ float As[2][BK2][BM];
    __shared__ float Bs[2][BK2][BN2];
    int bn = blockIdx.x;
    int bm = blockIdx.y;
    int tid = threadIdx.x;
    int tx = tid & 31;
    int ty = tid >> 5;
    int row0 = bm * BM;
    int col0 = (bn & 1) * BN2;

    const float* W;
    const float* bias;
    const float* hb;
    __half *P0, *P1;
    if (bn < 2) {
        W = W1; bias = b1; hb = g_hb1;
        P0 = g_pa0; P1 = g_pa1;
    } else {
        W = W2; bias = b2; hb = g_hb2;
        P0 = g_pb0; P1 = g_pb1;
    }

    int a_row = tid >> 1;
    int a_k4 = (tid & 1) * 4;
    int b_k = tid >> 5;
    int b_n8 = (tid & 31) * 8;

    const float* agp = ge + (size_t)(row0 + a_row) * DG + a_k4;
    const float* bgp = W + (size_t)b_k * OUTD + col0 + b_n8;

    float acc[TM][TN];
#pragma unroll
    for (int i = 0; i < TM; i++)
#pragma unroll
        for (int j = 0; j < TN; j++) acc[i][j] = 0.f;

    {
        float4 pa = *(const float4*)agp;
        float4 pb0 = *(const float4*)bgp;
        float4 pb1 = *(const float4*)(bgp + 4);
        As[0][a_k4 + 0][a_row] = pa.x;
        As[0][a_k4 + 1][a_row] = pa.y;
        As[0][a_k4 + 2][a_row] = pa.z;
        As[0][a_k4 + 3][a_row] = pa.w;
        *(float4*)&Bs[0][b_k][b_n8] = pb0;
        *(float4*)&Bs[0][b_k][b_n8 + 4] = pb1;
    }
    __syncthreads();

    for (int k0 = 0; k0 < DG; k0 += BK2) {
        int buf = (k0 >> 3) & 1;
        float4 pa, pb0, pb1;
        bool more = (k0 + BK2) < DG;
        if (more) {
            pa = *(const float4*)(agp + k0 + BK2);
            pb0 = *(const float4*)(bgp + (size_t)(k0 + BK2) * OUTD);
            pb1 = *(const float4*)(bgp + (size_t)(k0 + BK2) * OUTD + 4);
        }
#pragma unroll
        for (int kk = 0; kk < BK2; kk++) {
            float4 a0 = *(const float4*)&As[buf][kk][ty * TM];
            float4 a1v = *(const float4*)&As[buf][kk][ty * TM + 4];
            float4 a2v = *(const float4*)&As[buf][kk][ty * TM + 8];
            float4 a3v = *(const float4*)&As[buf][kk][ty * TM + 12];
            float4 bv0 = *(const float4*)&Bs[buf][kk][tx * TN];
            float4 bv1 = *(const float4*)&Bs[buf][kk][tx * TN + 4];
            float av[TM] = {a0.x, a0.y, a0.z, a0.w, a1v.x, a1v.y, a1v.z, a1v.w,
                            a2v.x, a2v.y, a2v.z, a2v.w, a3v.x, a3v.y, a3v.z, a3v.w};
            float bv[TN] = {bv0.x, bv0.y, bv0.z, bv0.w, bv1.x, bv1.y, bv1.z, bv1.w};
#pragma unroll
            for (int i = 0; i < TM; i++)
#pragma unroll
                for (int j = 0; j < TN; j++) acc[i][j] = fmaf(av[i], bv[j], acc[i][j]);
        }
        if (more) {
            int nb = buf ^ 1;
            As[nb][a_k4 + 0][a_row] = pa.x;
            As[nb][a_k4 + 1][a_row] = pa.y;
            As[nb][a_k4 + 2][a_row] = pa.z;
            As[nb][a_k4 + 3][a_row] = pa.w;
            *(float4*)&Bs[nb][b_k][b_n8] = pb0;
            *(float4*)&Bs[nb][b_k][b_n8 + 4] = pb1;
        }
        __syncthreads();
    }

    int b = row0 >> 11;
    float hbn[TN], bnn[TN];
#pragma unroll
    for (int j = 0; j < TN; j++) {
        int n = col0 + tx * TN + j;
        hbn[j] = hb[b * OUTD + n];
        bnn[j] = bias[n];
    }
#pragma unroll
    for (int i = 0; i < TM; i++) {
        int m = row0 + ty * TM + i;
        float mk = mask[m];
        size_t base = (size_t)m * OUTD + col0 + tx * TN;
        __half hh[TN], mm_[TN];
#pragma unroll
        for (int j = 0; j < TN; j++) {
            float o = mk * (acc[i][j] + hbn[j]) + bnn[j];
            __half h = __float2half_rn(o);
            float r = o - __half2float(h);
            hh[j] = h;
            mm_[j] = __float2half_rn(r);
        }
        *(uint4*)(P0 + base) = *(uint4*)hh;
        *(uint4*)(P1 + base) = *(uint4*)mm_;
    }
}

// ---- tensor-core gemm2 (fp16 2-way split, 3 terms hh/hm/mh; R11 pipeline config:
//      128x64 CTA tile, 32x32 warp tiles, 2 CTAs/SM, padded 2-stage cp.async) ----
#define KC2 32
#define ST2 40                      // padded row stride in fp16 elems (80B)
#define PLA (128 * ST2)             // A plane elems (5120)
#define PLB (64 * ST2)              // B plane elems (2560)
#define BUFE2 (2 * PLA + 2 * PLB)   // elems per buffer (15360)
#define SMEMB2 (2 * BUFE2 * 2)      // 61440 bytes
#define NCHK2 (OUTD / KC2)          // 16

__global__ __launch_bounds__(256, 2) void k_gemm2m(float* __restrict__ out) {
    extern __shared__ __half sm[];
    __shared__ unsigned int sMin;
    int tid = threadIdx.x;
    int wid = tid >> 5;
    int lane = tid & 31;
    int b = blockIdx.z;
    int row0 = blockIdx.y * 128;
    int col0 = blockIdx.x * 64;
    int wm = wid >> 1;  // 0..3 (32-row slices)
    int wn = wid & 1;   // 0..1 (32-col slices)

    if (tid == 0) sMin = 0xFFFFFFFFu;

    // loader geometry: 4 threads per row (16B each covering 64B = 32 fp16)
    int lrow = tid >> 2;       // 0..63
    int lg = (tid & 3) * 8;    // fp16 elem offset
    size_t rA0 = ((size_t)(b << 11) + row0 + lrow) * OUTD + lg;
    size_t rA1 = rA0 + (size_t)64 * OUTD;
    size_t rB = ((size_t)(b << 11) + col0 + lrow) * OUTD + lg;
    uint32_t smb = smem_u32(sm);
    uint32_t sA0 = smb + (uint32_t)(lrow * ST2 + lg) * 2;
    uint32_t sA1 = sA0 + 64 * ST2 * 2;
    uint32_t sB = smb + (uint32_t)(2 * PLA + lrow * ST2 + lg) * 2;

#define LOAD_CHUNK2(kk0, bufsel)                                        \
    do {                                                                \
        uint32_t bo_ = (uint32_t)(bufsel) * (BUFE2 * 2);                \
        cp16(sA0 + bo_ + 0 * (PLA * 2), g_pa0 + rA0 + (kk0));           \
        cp16(sA1 + bo_ + 0 * (PLA * 2), g_pa0 + rA1 + (kk0));           \
        cp16(sA0 + bo_ + 1 * (PLA * 2), g_pa1 + rA0 + (kk0));           \
        cp16(sA1 + bo_ + 1 * (PLA * 2), g_pa1 + rA1 + (kk0));           \
        cp16(sB + bo_ + 0 * (PLB * 2), g_pb0 + rB + (kk0));             \
        cp16(sB + bo_ + 1 * (PLB * 2), g_pb1 + rB + (kk0));             \
        CP_COMMIT();                                                    \
    } while (0)

    float shh[2][4][4], srest[2][4][4];
#pragma unroll
    for (int mf = 0; mf < 2; mf++)
#pragma unroll
        for (int nf = 0; nf < 4; nf++)
#pragma unroll
            for (int q = 0; q < 4; q++) {
                shh[mf][nf][q] = 0.f;
                srest[mf][nf][q] = 0.f;
            }

    LOAD_CHUNK2(0, 0);

    for (int c = 0; c < NCHK2; c++) {
        int buf = c & 1;
        uint32_t base = smb + buf * (BUFE2 * 2);
        bool more = (c + 1) < NCHK2;
        if (more) {
            LOAD_CHUNK2((c + 1) * KC2, buf ^ 1);
            CP_WAIT1();
        } else {
            CP_WAIT0();
        }
        __syncthreads();

#pragma unroll
        for (int s = 0; s < 2; s++) {
            uint32_t afr[2][2][4];
            uint32_t bfr[2][2][4];
            {
                int arow = wm * 32 + (lane & 15);
                int acol = s * 16 + (lane >> 4) * 8;
#pragma unroll
                for (int p = 0; p < 2; p++)
#pragma unroll
                    for (int mf = 0; mf < 2; mf++)
                        ldsm4(afr[p][mf],
                              base + (uint32_t)(p * PLA + (arow + mf * 16) * ST2 + acol) * 2);
                int nrow = wn * 32 + (lane & 7) + ((lane >> 4) & 1) * 8;
                int kcol = s * 16 + ((lane >> 3) & 1) * 8;
#pragma unroll
                for (int p = 0; p < 2; p++)
#pragma unroll
                    for (int g = 0; g < 2; g++)
                        ldsm4(bfr[p][g],
                              base + (uint32_t)(2 * PLA + p * PLB + (nrow + g * 16) * ST2 + kcol) * 2);
            }
            // term-outer: t=0 hh -> shh; t=1..2 hm, mh -> srest
            // (mm, hl, lh dropped: each ~2^-22 relative, incoherent sum ~3e-7 abs << chain noise)
            const int pa_t[3] = {0, 0, 1};
            const int pb_t[3] = {0, 1, 0};
#pragma unroll
            for (int t = 0; t < 3; t++) {
                int pa = pa_t[t], pb = pb_t[t];
                float (*dst)[4][4] = (t == 0) ? shh : srest;
#pragma unroll
                for (int mf = 0; mf < 2; mf++)
#pragma unroll
                    for (int nf = 0; nf < 4; nf++)
                        mma_f16(dst[mf][nf], afr[pa][mf],
                                bfr[pb][nf >> 1][(nf & 1) * 2],
                                bfr[pb][nf >> 1][(nf & 1) * 2 + 1]);
            }
        }
        __syncthreads();
    }

    // epilogue: v = rest + hh (one rounding) + fused per-batch min
    float lmin = 3.402823466e+38f;
    float* outb = out + (size_t)b * NN * NN;
#pragma unroll
    for (int mf = 0; mf < 2; mf++)
#pragma unroll
        for (int nf = 0; nf < 4; nf++) {
            int r = row0 + wm * 32 + mf * 16 + (lane >> 2);
            int cc = col0 + wn * 32 + nf * 8 + (lane & 3) * 2;
            float v0x = __fadd_rn(srest[mf][nf][0], shh[mf][nf][0]);
            float v0y = __fadd_rn(srest[mf][nf][1], shh[mf][nf][1]);
            float v1x = __fadd_rn(srest[mf][nf][2], shh[mf][nf][2]);
            float v1y = __fadd_rn(srest[mf][nf][3], shh[mf][nf][3]);
            *(float2*)(outb + (size_t)r * NN + cc) = make_float2(v0x, v0y);
            *(float2*)(outb + (size_t)(r + 8) * NN + cc) = make_float2(v1x, v1y);
            lmin = fminf(lmin, fminf(fminf(v0x, v0y), fminf(v1x, v1y)));
        }
#pragma unroll
    for (int off = 16; off > 0; off >>= 1)
        lmin = fminf(lmin, __shfl_xor_sync(0xFFFFFFFFu, lmin, off));
    __syncthreads();
    if (lane == 0) atomicMin(&sMin, fmap(lmin));
    __syncthreads();
    if (tid == 0) atomicMin(&g_minbits[b], sMin);
}

// ---------------- selection (per-warp histograms) / apply ----------------
#define RT 256
#define EPT 8
__global__ __launch_bounds__(RT) void k_sel(const float* __restrict__ out,
                                            const float* __restrict__ mask) {
    __shared__ unsigned int hist[8][256];   // per-warp private histograms
    __shared__ unsigned int warpsum[8];
    __shared__ unsigned int s_digit, s_r;
    __shared__ float s_part[8];

    int row = blockIdx.x;
    int b = row >> 11;
    int tid = threadIdx.x;
    int lane = tid & 31;
    int warp = tid >> 5;
    float minb = funmap(g_minbits[b]);
    float mk = mask[row];
    const float* rp = out + (size_t)row * NN;

    float v[EPT];
    unsigned int key[EPT];
    {
        float4 x0 = *(const float4*)(rp + tid * EPT);
        float4 x1 = *(const float4*)(rp + tid * EPT + 4);
        float xv[8] = {x0.x, x0.y, x0.z, x0.w, x1.x, x1.y, x1.z, x1.w};
#pragma unroll
        for (int q = 0; q < EPT; q++) {
            v[q] = (xv[q] - minb) * mk;
            key[q] = fmap(v[q]);
        }
    }

    unsigned int prefix = 0;
    unsigned int r = KTOP;
#pragma unroll
    for (int shift = 24; shift >= 0; shift -= 8) {
        unsigned int* hflat = &hist[0][0];
#pragma unroll
        for (int q = 0; q < 8; q++) hflat[tid + q * 256] = 0u;
        __syncthreads();
        unsigned int pmask = (shift == 24) ? 0u : (0xFFFFFFFFu << (shift + 8));
        unsigned int* hw = hist[warp];
#pragma unroll
        for (int q = 0; q < EPT; q++) {
            unsigned int k = key[q];
            if ((k & pmask) == prefix)
                atomicAdd(&hw[(k >> shift) & 0xFFu], 1u);
        }
        __syncthreads();
        unsigned int h = 0;
#pragma unroll
        for (int w = 0; w < 8; w++) h += hist[w][tid];
        unsigned int s = h;
#pragma unroll
        for (int off = 1; off < 32; off <<= 1) {
            unsigned int t = __shfl_down_sync(0xFFFFFFFFu, s, off);
            if (lane + off < 32) s += t;
        }
        if (lane == 0) warpsum[warp] = s;
        __syncthreads();
        unsigned int woff = 0;
#pragma unroll
        for (int w = 0; w < 8; w++)
            if (w > warp) woff += warpsum[w];
        unsigned int suffix = s + woff;
        if (suffix >= r && suffix - h < r) {
            s_digit = (unsigned int)tid;
            s_r = r - (suffix - h);
        }
        __syncthreads();
        prefix |= (s_digit << shift);
        r = s_r;
    }
    unsigned int T = prefix;
    unsigned int eq_needed = r;

    float lsum = 0.f;
#pragma unroll
    for (int q = 0; q < EPT; q++)
        if (key[q] > T) lsum += v[q];
#pragma unroll
    for (int off = 16; off > 0; off >>= 1) lsum += __shfl_xor_sync(0xFFFFFFFFu, lsum, off);
    if (lane == 0) s_part[warp] = lsum;
    __syncthreads();
    if (tid == 0) {
        float tot = 0.f;
#pragma unroll
        for (int w = 0; w < 8; w++) tot += s_part[w];
        tot += (float)eq_needed * funmap(T);
        float d = (tot > 0.f) ? (1.0f / sqrtf(tot)) : 0.0f;
        g_dinv[row] = d;
        g_T[row] = T;
        g_eq[row] = eq_needed;
    }
}

__global__ __launch_bounds__(RT) void k_apply(float* __restrict__ out,
                                              const float* __restrict__ mask) {
    __shared__ unsigned int s_w[8];

    int row = blockIdx.x;
    int b = row >> 11;
    int tid = threadIdx.x;
    int lane = tid & 31;
    int warp = tid >> 5;
    float minb = funmap(g_minbits[b]);
    float mk = mask[row];
    unsigned int T = g_T[row];
    unsigned int eq = g_eq[row];
    float di = g_dinv[row];
    float* rp = out + (size_t)row * NN;

    float v[EPT];
    unsigned int key[EPT];
    {
        float4 x0 = *(const float4*)(rp + tid * EPT);
        float4 x1 = *(const float4*)(rp + tid * EPT + 4);
        float xv[8] = {x0.x, x0.y, x0.z, x0.w, x1.x, x1.y, x1.z, x1.w};
#pragma unroll
        for (int q = 0; q < EPT; q++) {
            v[q] = (xv[q] - minb) * mk;
            key[q] = fmap(v[q]);
        }
    }

    unsigned int cnt = 0;
#pragma unroll
    for (int q = 0; q < EPT; q++) cnt += (key[q] == T) ? 1u : 0u;
    unsigned int incl = cnt;
#pragma unroll
    for (int off = 1; off < 32; off <<= 1) {
        unsigned int t = __shfl_up_sync(0xFFFFFFFFu, incl, off);
        if (lane >= off) incl += t;
    }
    if (lane == 31) s_w[warp] = incl;
    __syncthreads();
    unsigned int woff = 0;
#pragma unroll
    for (int w = 0; w < 8; w++)
        if (w < warp) woff += s_w[w];
    unsigned int rank = woff + incl - cnt;

    float dj[EPT];
    {
        float4 d0 = *(const float4*)(g_dinv + ((size_t)b << 11) + tid * EPT);
        float4 d1 = *(const float4*)(g_dinv + ((size_t)b << 11) + tid * EPT + 4);
        dj[0] = d0.x; dj[1] = d0.y; dj[2] = d0.z; dj[3] = d0.w;
        dj[4] = d1.x; dj[5] = d1.y; dj[6] = d1.z; dj[7] = d1.w;
    }

    float o[EPT];
#pragma unroll
    for (int q = 0; q < EPT; q++) {
        unsigned int k = key[q];
        bool keep = (k > T) || (k == T && rank < eq);
        if (k == T) rank++;
        o[q] = keep ? (di * v[q]) * dj[q] : 0.0f;
    }
    float4 y0 = make_float4(o[0], o[1], o[2], o[3]);
    float4 y1 = make_float4(o[4], o[5], o[6], o[7]);
    *(float4*)(rp + tid * EPT) = y0;
    *(float4*)(rp + tid * EPT + 4) = y1;
}

extern "C" void kernel_launch(void* const* d_in, const int* in_sizes, int n_in,
                              void* d_out, int out_size) {
    const float* ge = (const float*)d_in[0];
    const float* mask = (const float*)d_in[1];
    const float* hs = (const float*)d_in[2];
    const float* W1 = (const float*)d_in[3];
    const float* b1 = (const float*)d_in[4];
    const float* W2 = (const float*)d_in[5];
    const float* b2 = (const float*)d_in[6];
    float* out = (float*)d_out;

    cudaFuncSetAttribute(k_gemm2m, cudaFuncAttributeMaxDynamicSharedMemorySize, SMEMB2);

    k_hb<<<BB, 512>>>(hs, W1, W2);
    k_gemm1<<<dim3(4, (BB * NN) / BM), 256>>>(ge, mask, W1, b1, W2, b2);
    k_gemm2m<<<dim3(NN / 64, NN / 128, BB), 256, SMEMB2>>>(out);
    k_sel<<<BB * NN, RT>>>(out, mask);
    k_apply<<<BB * NN, RT>>>(out, mask);
}